// round 1
// baseline (speedup 1.0000x reference)
#include <cuda_runtime.h>
#include <math.h>

#define BB     2
#define KSTEP  512
#define SDIM   60
#define NACT   5
#define EE     256
#define HH     4
#define DD     64
#define FFD    1024
#define NLAYER 2
#define LL     1536          // 3*KSTEP
#define MTOK   3072          // BB*LL
#define CHUNK  64
#define NCH    24            // LL/CHUNK
#define NBH    8             // BB*HH

// ---------------- scratch (device globals; no allocation) ----------------
__device__ float g_x  [MTOK * EE];
__device__ float g_xn [MTOK * EE];
__device__ float g_qkv[MTOK * 3 * EE];
__device__ float g_o  [MTOK * EE];
__device__ float g_ff [MTOK * FFD];
__device__ float g_S  [NBH * NCH * DD * DD];
__device__ float g_ks [NBH * NCH * DD];

// ---------------- embed: interleaved (rtg, state, action) + pos ----------
__global__ __launch_bounds__(256) void embed_kernel(
    const float* __restrict__ rtg, const float* __restrict__ state,
    const float* __restrict__ action,
    const float* __restrict__ rtg_w, const float* __restrict__ rtg_b,
    const float* __restrict__ state_w, const float* __restrict__ state_b,
    const float* __restrict__ action_w, const float* __restrict__ action_b,
    const float* __restrict__ pos, float* __restrict__ x)
{
    int tok = blockIdx.x;          // 0..MTOK-1
    int e   = threadIdx.x;         // 0..255
    int b   = tok / LL;
    int l   = tok % LL;
    int k   = l / 3;
    int typ = l % 3;
    float acc = pos[k * EE + e];
    if (typ == 0) {
        acc += rtg[b * KSTEP + k] * rtg_w[e] + rtg_b[e];
    } else if (typ == 1) {
        const float* s = state + (b * KSTEP + k) * SDIM;
        float sum = 0.f;
        for (int i = 0; i < SDIM; i++) sum += s[i] * state_w[i * EE + e];
        acc += sum + state_b[e];
    } else {
        const float* a = action + (b * KSTEP + k) * NACT;
        float sum = 0.f;
#pragma unroll
        for (int i = 0; i < NACT; i++) sum += a[i] * action_w[i * EE + e];
        acc += sum + action_b[e];
    }
    x[tok * EE + e] = acc;
}

// ---------------- LayerNorm: one block per row -----------------------------
__global__ __launch_bounds__(256) void ln_kernel(
    const float* __restrict__ x, const float* __restrict__ g,
    const float* __restrict__ bta, float* __restrict__ y)
{
    int row = blockIdx.x;
    int e   = threadIdx.x;
    __shared__ float red[8];
    float v = x[row * EE + e];

    float s = v;
#pragma unroll
    for (int o = 16; o; o >>= 1) s += __shfl_xor_sync(0xffffffffu, s, o);
    if ((e & 31) == 0) red[e >> 5] = s;
    __syncthreads();
    float total;
    if (e < 8) {
        float t = red[e];
#pragma unroll
        for (int o = 4; o; o >>= 1) t += __shfl_xor_sync(0xffu, t, o);
        if (e == 0) red[0] = t;
    }
    __syncthreads();
    float mean = red[0] * (1.0f / EE);
    __syncthreads();

    float d  = v - mean;
    float s2 = d * d;
#pragma unroll
    for (int o = 16; o; o >>= 1) s2 += __shfl_xor_sync(0xffffffffu, s2, o);
    if ((e & 31) == 0) red[e >> 5] = s2;
    __syncthreads();
    if (e < 8) {
        float t = red[e];
#pragma unroll
        for (int o = 4; o; o >>= 1) t += __shfl_xor_sync(0xffu, t, o);
        if (e == 0) red[0] = t;
    }
    __syncthreads();
    float var = red[0] * (1.0f / EE);
    float r = rsqrtf(var + 1e-5f);
    y[row * EE + e] = d * r * g[e] + bta[e];
}

// ---------------- SGEMM: C[M,N] = A[M,K] @ W[K,N] + bias (+epilogue) -------
// EPI: 0 = bias, 1 = bias + exact GELU, 2 = bias + residual add
__device__ __forceinline__ float gelu_exact(float x) {
    return 0.5f * x * (1.0f + erff(x * 0.70710678118654752f));
}

template <int EPI>
__global__ __launch_bounds__(256) void gemm_kernel(
    const float* __restrict__ A, const float* __restrict__ W,
    const float* __restrict__ bias, const float* __restrict__ Res,
    float* __restrict__ C, int M, int N, int K)
{
    __shared__ float As[16][64];
    __shared__ float Bs[16][64];

    int tid = threadIdx.x;
    int tx = tid & 15;       // n-group
    int ty = tid >> 4;       // m-group
    int m0 = blockIdx.y * 64;
    int n0 = blockIdx.x * 64;

    float acc[4][4] = {};

    for (int k0 = 0; k0 < K; k0 += 16) {
#pragma unroll
        for (int i = tid; i < 64 * 16; i += 256) {
            int m = i >> 4, kk = i & 15;
            As[kk][m] = A[(m0 + m) * K + k0 + kk];
        }
#pragma unroll
        for (int i = tid; i < 16 * 64; i += 256) {
            int kk = i >> 6, n = i & 63;
            Bs[kk][n] = W[(k0 + kk) * N + n0 + n];
        }
        __syncthreads();
#pragma unroll
        for (int kk = 0; kk < 16; kk++) {
            float4 a4 = *(const float4*)&As[kk][ty * 4];
            float4 b4 = *(const float4*)&Bs[kk][tx * 4];
            float ar[4] = {a4.x, a4.y, a4.z, a4.w};
            float br[4] = {b4.x, b4.y, b4.z, b4.w};
#pragma unroll
            for (int i = 0; i < 4; i++)
#pragma unroll
                for (int j = 0; j < 4; j++)
                    acc[i][j] += ar[i] * br[j];
        }
        __syncthreads();
    }

#pragma unroll
    for (int i = 0; i < 4; i++) {
        int m = m0 + ty * 4 + i;
#pragma unroll
        for (int j = 0; j < 4; j++) {
            int n = n0 + tx * 4 + j;
            float c = acc[i][j] + bias[n];
            if (EPI == 1) c = gelu_exact(c);
            if (EPI == 2) c += Res[m * N + n];
            C[m * N + n] = c;
        }
    }
}

// ---------------- attention pass A: per-chunk sums --------------------------
__global__ __launch_bounds__(256) void attn_chunksum_kernel(
    const float* __restrict__ qkv, float* __restrict__ S, float* __restrict__ ks)
{
    __shared__ float Ks[64 * 65];
    __shared__ float Vs[64 * 65];
    int blk = blockIdx.x;
    int bh = blk / NCH, c = blk % NCH;
    int b = bh / HH, h = bh % HH;
    int tid = threadIdx.x;

    for (int i = tid; i < 4096; i += 256) {
        int t = i >> 6, d = i & 63;
        int row = b * LL + c * CHUNK + t;
        float kv = qkv[row * 768 + 256 + h * 64 + d];
        Ks[t * 65 + d] = fmaxf(kv, 0.f) + 1e-6f;
        Vs[t * 65 + d] = qkv[row * 768 + 512 + h * 64 + d];
    }
    __syncthreads();

    int d0 = (tid >> 4) * 4, e0 = (tid & 15) * 4;
    float acc[4][4] = {};
    for (int t = 0; t < 64; t++) {
        float kd[4], ve[4];
#pragma unroll
        for (int i = 0; i < 4; i++) kd[i] = Ks[t * 65 + d0 + i];
#pragma unroll
        for (int j = 0; j < 4; j++) ve[j] = Vs[t * 65 + e0 + j];
#pragma unroll
        for (int i = 0; i < 4; i++)
#pragma unroll
            for (int j = 0; j < 4; j++)
                acc[i][j] += kd[i] * ve[j];
    }
    float* So = S + (bh * NCH + c) * 4096;
#pragma unroll
    for (int i = 0; i < 4; i++)
#pragma unroll
        for (int j = 0; j < 4; j++)
            So[(d0 + i) * 64 + e0 + j] = acc[i][j];

    if (tid < 64) {
        float s = 0.f;
        for (int t = 0; t < 64; t++) s += Ks[t * 65 + tid];
        ks[(bh * NCH + c) * 64 + tid] = s;
    }
}

// ---------------- attention pass B: exclusive prefix over chunks -----------
__global__ __launch_bounds__(256) void attn_scan_kernel(
    float* __restrict__ S, float* __restrict__ ks)
{
    int bh = blockIdx.x;
    int tid = threadIdx.x;
    for (int e = tid; e < 4096; e += 256) {
        float carry = 0.f;
        for (int c = 0; c < NCH; c++) {
            float* p = &S[(bh * NCH + c) * 4096 + e];
            float t = *p; *p = carry; carry += t;
        }
    }
    if (tid < 64) {
        float carry = 0.f;
        for (int c = 0; c < NCH; c++) {
            float* p = &ks[(bh * NCH + c) * 64 + tid];
            float t = *p; *p = carry; carry += t;
        }
    }
}

// ---------------- attention pass C: per-chunk output -----------------------
__global__ __launch_bounds__(256) void attn_out_kernel(
    const float* __restrict__ qkv, const float* __restrict__ S,
    const float* __restrict__ ks, float* __restrict__ o)
{
    extern __shared__ float sm[];
    float* Qs   = sm;             // 64x65 (relu(q)+eps)
    float* Ts   = sm + 4160;      // 64x65 temp: P, then K, then V
    float* As   = sm + 8320;      // 64x65 masked QK^T
    float* dens = sm + 12480;     // 64
    float* kps  = dens + 64;      // 64

    int blk = blockIdx.x;
    int bh = blk / NCH, c = blk % NCH;
    int b = bh / HH, h = bh % HH;
    int tid = threadIdx.x;
    const float* Sc = S  + (bh * NCH + c) * 4096;
    const float* kc = ks + (bh * NCH + c) * 64;

    // load Q (phi applied) and P (exclusive kv prefix)
    for (int i = tid; i < 4096; i += 256) {
        int t = i >> 6, d = i & 63;
        int row = b * LL + c * CHUNK + t;
        float qv = qkv[row * 768 + h * 64 + d];
        Qs[t * 65 + d] = fmaxf(qv, 0.f) + 1e-6f;
        Ts[t * 65 + d] = Sc[i];          // P[d][e] (t=d, d=e here)
    }
    if (tid < 64) kps[tid] = kc[tid];
    __syncthreads();

    int i0 = (tid >> 4) * 4, j0 = (tid & 15) * 4;
    float acc[4][4] = {};

    // acc = Q @ P
    for (int d = 0; d < 64; d++) {
        float q[4], p[4];
#pragma unroll
        for (int i = 0; i < 4; i++) q[i] = Qs[(i0 + i) * 65 + d];
#pragma unroll
        for (int j = 0; j < 4; j++) p[j] = Ts[d * 65 + j0 + j];
#pragma unroll
        for (int i = 0; i < 4; i++)
#pragma unroll
            for (int j = 0; j < 4; j++)
                acc[i][j] += q[i] * p[j];
    }
    if (tid < 64) {
        float s = 0.f;
        for (int d = 0; d < 64; d++) s += Qs[tid * 65 + d] * kps[d];
        dens[tid] = s;
    }
    __syncthreads();

    // load K (phi applied)
    for (int i = tid; i < 4096; i += 256) {
        int t = i >> 6, d = i & 63;
        int row = b * LL + c * CHUNK + t;
        float kv = qkv[row * 768 + 256 + h * 64 + d];
        Ts[t * 65 + d] = fmaxf(kv, 0.f) + 1e-6f;
    }
    __syncthreads();

    // A = tril(Q K^T)
    {
        float av[4][4] = {};
        for (int d = 0; d < 64; d++) {
            float q[4], kk[4];
#pragma unroll
            for (int i = 0; i < 4; i++) q[i]  = Qs[(i0 + i) * 65 + d];
#pragma unroll
            for (int j = 0; j < 4; j++) kk[j] = Ts[(j0 + j) * 65 + d];
#pragma unroll
            for (int i = 0; i < 4; i++)
#pragma unroll
                for (int j = 0; j < 4; j++)
                    av[i][j] += q[i] * kk[j];
        }
#pragma unroll
        for (int i = 0; i < 4; i++)
#pragma unroll
            for (int j = 0; j < 4; j++)
                As[(i0 + i) * 65 + (j0 + j)] = ((j0 + j) <= (i0 + i)) ? av[i][j] : 0.f;
    }
    __syncthreads();

    // den += rowsum(A); load V
    if (tid < 64) {
        float rs = 0.f;
        for (int j = 0; j < 64; j++) rs += As[tid * 65 + j];
        dens[tid] += rs;
    }
    for (int i = tid; i < 4096; i += 256) {
        int t = i >> 6, d = i & 63;
        int row = b * LL + c * CHUNK + t;
        Ts[t * 65 + d] = qkv[row * 768 + 512 + h * 64 + d];
    }
    __syncthreads();

    // acc += A @ V; write o = acc / max(den, 1e-6)
    for (int j = 0; j < 64; j++) {
        float av[4], vv[4];
#pragma unroll
        for (int i = 0; i < 4; i++) av[i] = As[(i0 + i) * 65 + j];
#pragma unroll
        for (int jj = 0; jj < 4; jj++) vv[jj] = Ts[j * 65 + j0 + jj];
#pragma unroll
        for (int i = 0; i < 4; i++)
#pragma unroll
            for (int jj = 0; jj < 4; jj++)
                acc[i][jj] += av[i] * vv[jj];
    }
#pragma unroll
    for (int i = 0; i < 4; i++) {
        float dn = fmaxf(dens[i0 + i], 1e-6f);
        int row = b * LL + c * CHUNK + i0 + i;
        float inv = 1.0f / dn;
#pragma unroll
        for (int j = 0; j < 4; j++)
            o[row * EE + h * 64 + j0 + j] = acc[i][j] * inv;
    }
}

// ---------------- pred: state tokens @ pred_w + pred_b ---------------------
__global__ __launch_bounds__(256) void pred_kernel(
    const float* __restrict__ xn, const float* __restrict__ pred_w,
    const float* __restrict__ pred_b, float* __restrict__ out)
{
    int bk = blockIdx.x;                 // 0..B*K-1
    int b = bk / KSTEP, k = bk % KSTEP;
    int row = b * LL + 3 * k + 1;
    __shared__ float xr[EE];
    int tid = threadIdx.x;
    xr[tid] = xn[row * EE + tid];
    __syncthreads();
    int w = tid >> 5, lane = tid & 31;
    if (w < NACT) {
        float s = 0.f;
        for (int e = lane; e < EE; e += 32) s += xr[e] * pred_w[e * NACT + w];
#pragma unroll
        for (int o = 16; o; o >>= 1) s += __shfl_xor_sync(0xffffffffu, s, o);
        if (lane == 0) out[bk * NACT + w] = s + pred_b[w];
    }
}

// ---------------- launch ----------------------------------------------------
extern "C" void kernel_launch(void* const* d_in, const int* in_sizes, int n_in,
                              void* d_out, int out_size)
{
    const float* rtg      = (const float*)d_in[0];
    const float* state    = (const float*)d_in[1];
    const float* action   = (const float*)d_in[2];
    const float* rtg_w    = (const float*)d_in[3];
    const float* rtg_b    = (const float*)d_in[4];
    const float* state_w  = (const float*)d_in[5];
    const float* state_b  = (const float*)d_in[6];
    const float* action_w = (const float*)d_in[7];
    const float* action_b = (const float*)d_in[8];
    const float* pos_emb  = (const float*)d_in[9];
    const float* norm1_g  = (const float*)d_in[10];
    const float* norm1_b  = (const float*)d_in[11];
    const float* qkv_w    = (const float*)d_in[12];
    const float* qkv_b    = (const float*)d_in[13];
    const float* out_w    = (const float*)d_in[14];
    const float* out_b    = (const float*)d_in[15];
    const float* norm2_g  = (const float*)d_in[16];
    const float* norm2_b  = (const float*)d_in[17];
    const float* ffn1_w   = (const float*)d_in[18];
    const float* ffn1_b   = (const float*)d_in[19];
    const float* ffn2_w   = (const float*)d_in[20];
    const float* ffn2_b   = (const float*)d_in[21];
    const float* normf_g  = (const float*)d_in[22];
    const float* normf_b  = (const float*)d_in[23];
    const float* pred_w   = (const float*)d_in[24];
    const float* pred_b   = (const float*)d_in[25];

    float *x, *xn, *qkv, *o, *ff, *S, *ks;
    cudaGetSymbolAddress((void**)&x,   g_x);
    cudaGetSymbolAddress((void**)&xn,  g_xn);
    cudaGetSymbolAddress((void**)&qkv, g_qkv);
    cudaGetSymbolAddress((void**)&o,   g_o);
    cudaGetSymbolAddress((void**)&ff,  g_ff);
    cudaGetSymbolAddress((void**)&S,   g_S);
    cudaGetSymbolAddress((void**)&ks,  g_ks);

    const int SMEM_C = (4160 * 3 + 128) * sizeof(float);  // 50432 B
    cudaFuncSetAttribute(attn_out_kernel,
                         cudaFuncAttributeMaxDynamicSharedMemorySize, SMEM_C);

    embed_kernel<<<MTOK, 256>>>(rtg, state, action, rtg_w, rtg_b, state_w, state_b,
                                action_w, action_b, pos_emb, x);

    for (int layer = 0; layer < NLAYER; layer++) {
        const float* n1g = norm1_g + layer * EE;
        const float* n1b = norm1_b + layer * EE;
        const float* n2g = norm2_g + layer * EE;
        const float* n2b = norm2_b + layer * EE;
        const float* qw  = qkv_w  + layer * EE * 3 * EE;
        const float* qb  = qkv_b  + layer * 3 * EE;
        const float* ow  = out_w  + layer * EE * EE;
        const float* ob  = out_b  + layer * EE;
        const float* f1w = ffn1_w + layer * EE * FFD;
        const float* f1b = ffn1_b + layer * FFD;
        const float* f2w = ffn2_w + layer * FFD * EE;
        const float* f2b = ffn2_b + layer * EE;

        ln_kernel<<<MTOK, 256>>>(x, n1g, n1b, xn);
        gemm_kernel<0><<<dim3(768 / 64, MTOK / 64), 256>>>(xn, qw, qb, nullptr, qkv,
                                                           MTOK, 768, EE);
        attn_chunksum_kernel<<<NBH * NCH, 256>>>(qkv, S, ks);
        attn_scan_kernel<<<NBH, 256>>>(S, ks);
        attn_out_kernel<<<NBH * NCH, 256, SMEM_C>>>(qkv, S, ks, o);
        gemm_kernel<2><<<dim3(EE / 64, MTOK / 64), 256>>>(o, ow, ob, x, x,
                                                          MTOK, EE, EE);
        ln_kernel<<<MTOK, 256>>>(x, n2g, n2b, xn);
        gemm_kernel<1><<<dim3(FFD / 64, MTOK / 64), 256>>>(xn, f1w, f1b, nullptr, ff,
                                                           MTOK, FFD, EE);
        gemm_kernel<2><<<dim3(EE / 64, MTOK / 64), 256>>>(ff, f2w, f2b, x, x,
                                                          MTOK, EE, FFD);
    }

    ln_kernel<<<MTOK, 256>>>(x, normf_g, normf_b, xn);
    pred_kernel<<<BB * KSTEP, 256>>>(xn, pred_w, pred_b, (float*)d_out);
}

// round 2
// speedup vs baseline: 1.2802x; 1.2802x over previous
#include <cuda_runtime.h>
#include <math.h>

#define BB     2
#define KSTEP  512
#define SDIM   60
#define NACT   5
#define EE     256
#define HH     4
#define DD     64
#define FFD    1024
#define NLAYER 2
#define LL     1536          // 3*KSTEP
#define MTOK   3072          // BB*LL
#define CHUNK  64
#define NCH    24            // LL/CHUNK
#define NBH    8             // BB*HH

// ---------------- scratch (device globals; no allocation) ----------------
__device__ float g_x  [MTOK * EE];
__device__ float g_xn [MTOK * EE];
__device__ float g_qkv[MTOK * 3 * EE];
__device__ float g_o  [MTOK * EE];
__device__ float g_ff [MTOK * FFD];
__device__ float g_sp [4 * MTOK * EE];     // split-K partials
__device__ float g_S  [NBH * NCH * DD * DD];
__device__ float g_ks [NBH * NCH * DD];

// ---------------- embed: interleaved (rtg, state, action) + pos ----------
__global__ __launch_bounds__(256) void embed_kernel(
    const float* __restrict__ rtg, const float* __restrict__ state,
    const float* __restrict__ action,
    const float* __restrict__ rtg_w, const float* __restrict__ rtg_b,
    const float* __restrict__ state_w, const float* __restrict__ state_b,
    const float* __restrict__ action_w, const float* __restrict__ action_b,
    const float* __restrict__ pos, float* __restrict__ x)
{
    int tok = blockIdx.x;
    int e   = threadIdx.x;
    int b   = tok / LL;
    int l   = tok % LL;
    int k   = l / 3;
    int typ = l % 3;
    float acc = pos[k * EE + e];
    if (typ == 0) {
        acc += rtg[b * KSTEP + k] * rtg_w[e] + rtg_b[e];
    } else if (typ == 1) {
        const float* s = state + (b * KSTEP + k) * SDIM;
        float sum = 0.f;
        for (int i = 0; i < SDIM; i++) sum += s[i] * state_w[i * EE + e];
        acc += sum + state_b[e];
    } else {
        const float* a = action + (b * KSTEP + k) * NACT;
        float sum = 0.f;
#pragma unroll
        for (int i = 0; i < NACT; i++) sum += a[i] * action_w[i * EE + e];
        acc += sum + action_b[e];
    }
    x[tok * EE + e] = acc;
}

// ---------------- LayerNorm: one block per row -----------------------------
__global__ __launch_bounds__(256) void ln_kernel(
    const float* __restrict__ x, const float* __restrict__ g,
    const float* __restrict__ bta, float* __restrict__ y)
{
    int row = blockIdx.x;
    int e   = threadIdx.x;
    __shared__ float red[8];
    float v = x[row * EE + e];

    float s = v;
#pragma unroll
    for (int o = 16; o; o >>= 1) s += __shfl_xor_sync(0xffffffffu, s, o);
    if ((e & 31) == 0) red[e >> 5] = s;
    __syncthreads();
    if (e < 8) {
        float t = red[e];
#pragma unroll
        for (int o = 4; o; o >>= 1) t += __shfl_xor_sync(0xffu, t, o);
        if (e == 0) red[0] = t;
    }
    __syncthreads();
    float mean = red[0] * (1.0f / EE);
    __syncthreads();

    float d  = v - mean;
    float s2 = d * d;
#pragma unroll
    for (int o = 16; o; o >>= 1) s2 += __shfl_xor_sync(0xffffffffu, s2, o);
    if ((e & 31) == 0) red[e >> 5] = s2;
    __syncthreads();
    if (e < 8) {
        float t = red[e];
#pragma unroll
        for (int o = 4; o; o >>= 1) t += __shfl_xor_sync(0xffu, t, o);
        if (e == 0) red[0] = t;
    }
    __syncthreads();
    float var = red[0] * (1.0f / EE);
    float r = rsqrtf(var + 1e-5f);
    y[row * EE + e] = d * r * g[e] + bta[e];
}

// ---------------- big SGEMM: 128x128 tile, 8x8 microtile, double-buffered --
// EPI: 0 = bias, 1 = bias + exact GELU, 3 = raw split-K partial (no bias)
__device__ __forceinline__ float gelu_exact(float x) {
    return 0.5f * x * (1.0f + erff(x * 0.70710678118654752f));
}

template <int EPI>
__global__ __launch_bounds__(256) void gemm128_kernel(
    const float* __restrict__ A, const float* __restrict__ W,
    const float* __restrict__ bias, float* __restrict__ C,
    int M, int N, int K)
{
    __shared__ float As[2][8][128];
    __shared__ float Bs[2][8][128];

    const int tid = threadIdx.x;
    const int m0 = blockIdx.y * 128;
    const int n0 = blockIdx.x * 128;
    const int ks   = K / gridDim.z;
    const int kbeg = blockIdx.z * ks;

    const int arow = tid >> 1, acol = (tid & 1) * 4;
    const int brow = tid >> 5, bcol = (tid & 31) * 4;

    const float* Ap = A + (size_t)(m0 + arow) * K + kbeg + acol;
    const float* Bp = W + (size_t)(kbeg + brow) * N + n0 + bcol;

    float4 a4 = *(const float4*)Ap;
    float4 b4 = *(const float4*)Bp;
    As[0][acol + 0][arow] = a4.x;
    As[0][acol + 1][arow] = a4.y;
    As[0][acol + 2][arow] = a4.z;
    As[0][acol + 3][arow] = a4.w;
    *(float4*)&Bs[0][brow][bcol] = b4;
    __syncthreads();

    float acc[8][8] = {};
    const int ma = (tid >> 4) * 8;
    const int na = (tid & 15) * 8;
    int buf = 0;

    for (int k0 = 8; k0 <= ks; k0 += 8) {
        const bool more = (k0 < ks);
        if (more) {
            a4 = *(const float4*)(Ap + k0);
            b4 = *(const float4*)(Bp + (size_t)k0 * N);
        }
#pragma unroll
        for (int kk = 0; kk < 8; kk++) {
            float a[8], b[8];
            *(float4*)(a)     = *(const float4*)&As[buf][kk][ma];
            *(float4*)(a + 4) = *(const float4*)&As[buf][kk][ma + 4];
            *(float4*)(b)     = *(const float4*)&Bs[buf][kk][na];
            *(float4*)(b + 4) = *(const float4*)&Bs[buf][kk][na + 4];
#pragma unroll
            for (int i = 0; i < 8; i++)
#pragma unroll
                for (int j = 0; j < 8; j++)
                    acc[i][j] += a[i] * b[j];
        }
        if (more) {
            buf ^= 1;
            As[buf][acol + 0][arow] = a4.x;
            As[buf][acol + 1][arow] = a4.y;
            As[buf][acol + 2][arow] = a4.z;
            As[buf][acol + 3][arow] = a4.w;
            *(float4*)&Bs[buf][brow][bcol] = b4;
            __syncthreads();
        }
    }

    if (EPI == 3) {
        float* Cp = C + (size_t)blockIdx.z * M * N;
#pragma unroll
        for (int i = 0; i < 8; i++) {
            int m = m0 + ma + i;
            float4 o1 = make_float4(acc[i][0], acc[i][1], acc[i][2], acc[i][3]);
            float4 o2 = make_float4(acc[i][4], acc[i][5], acc[i][6], acc[i][7]);
            *(float4*)&Cp[(size_t)m * N + n0 + na]     = o1;
            *(float4*)&Cp[(size_t)m * N + n0 + na + 4] = o2;
        }
    } else {
        float bs[8];
#pragma unroll
        for (int j = 0; j < 8; j++) bs[j] = bias[n0 + na + j];
#pragma unroll
        for (int i = 0; i < 8; i++) {
            int m = m0 + ma + i;
            float o[8];
#pragma unroll
            for (int j = 0; j < 8; j++) {
                float c = acc[i][j] + bs[j];
                if (EPI == 1) c = gelu_exact(c);
                o[j] = c;
            }
            *(float4*)&C[(size_t)m * N + n0 + na]     = *(float4*)(o);
            *(float4*)&C[(size_t)m * N + n0 + na + 4] = *(float4*)(o + 4);
        }
    }
}

// ---------------- split-K reduce: out = sum(sp) + bias + res ---------------
template <int NS>
__global__ __launch_bounds__(256) void reduce_kernel(
    const float* __restrict__ sp, const float* __restrict__ bias,
    const float* __restrict__ res, float* __restrict__ out)
{
    const int MN = MTOK * EE;
    int i = (blockIdx.x * 256 + threadIdx.x) * 4;
    float4 s = *(const float4*)&sp[i];
#pragma unroll
    for (int z = 1; z < NS; z++) {
        float4 t = *(const float4*)&sp[(size_t)z * MN + i];
        s.x += t.x; s.y += t.y; s.z += t.z; s.w += t.w;
    }
    int n = i & (EE - 1);
    float4 bv = *(const float4*)&bias[n];
    float4 rv = *(const float4*)&res[i];
    s.x += bv.x + rv.x; s.y += bv.y + rv.y;
    s.z += bv.z + rv.z; s.w += bv.w + rv.w;
    *(float4*)&out[i] = s;
}

// ---------------- attention pass A: per-chunk sums --------------------------
__global__ __launch_bounds__(256) void attn_chunksum_kernel(
    const float* __restrict__ qkv, float* __restrict__ S, float* __restrict__ ks)
{
    __shared__ float Ks[64 * 65];
    __shared__ float Vs[64 * 65];
    int blk = blockIdx.x;
    int bh = blk / NCH, c = blk % NCH;
    int b = bh / HH, h = bh % HH;
    int tid = threadIdx.x;

    for (int i = tid; i < 4096; i += 256) {
        int t = i >> 6, d = i & 63;
        int row = b * LL + c * CHUNK + t;
        float kv = qkv[row * 768 + 256 + h * 64 + d];
        Ks[t * 65 + d] = fmaxf(kv, 0.f) + 1e-6f;
        Vs[t * 65 + d] = qkv[row * 768 + 512 + h * 64 + d];
    }
    __syncthreads();

    int d0 = (tid >> 4) * 4, e0 = (tid & 15) * 4;
    float acc[4][4] = {};
    for (int t = 0; t < 64; t++) {
        float kd[4], ve[4];
#pragma unroll
        for (int i = 0; i < 4; i++) kd[i] = Ks[t * 65 + d0 + i];
#pragma unroll
        for (int j = 0; j < 4; j++) ve[j] = Vs[t * 65 + e0 + j];
#pragma unroll
        for (int i = 0; i < 4; i++)
#pragma unroll
            for (int j = 0; j < 4; j++)
                acc[i][j] += kd[i] * ve[j];
    }
    float* So = S + (bh * NCH + c) * 4096;
#pragma unroll
    for (int i = 0; i < 4; i++)
#pragma unroll
        for (int j = 0; j < 4; j++)
            So[(d0 + i) * 64 + e0 + j] = acc[i][j];

    if (tid < 64) {
        float s = 0.f;
        for (int t = 0; t < 64; t++) s += Ks[t * 65 + tid];
        ks[(bh * NCH + c) * 64 + tid] = s;
    }
}

// ---------------- attention pass B: exclusive prefix over chunks -----------
__global__ __launch_bounds__(256) void attn_scan_kernel(
    float* __restrict__ S, float* __restrict__ ks)
{
    int bh = blockIdx.x;
    int tid = threadIdx.x;
    for (int e = tid; e < 4096; e += 256) {
        float carry = 0.f;
        for (int c = 0; c < NCH; c++) {
            float* p = &S[(bh * NCH + c) * 4096 + e];
            float t = *p; *p = carry; carry += t;
        }
    }
    if (tid < 64) {
        float carry = 0.f;
        for (int c = 0; c < NCH; c++) {
            float* p = &ks[(bh * NCH + c) * 64 + tid];
            float t = *p; *p = carry; carry += t;
        }
    }
}

// ---------------- attention pass C: per-chunk output -----------------------
__global__ __launch_bounds__(256) void attn_out_kernel(
    const float* __restrict__ qkv, const float* __restrict__ S,
    const float* __restrict__ ks, float* __restrict__ o)
{
    extern __shared__ float sm[];
    float* Qs   = sm;             // 64x65 (relu(q)+eps)
    float* Ts   = sm + 4160;      // 64x65 temp: P, then K, then V
    float* As   = sm + 8320;      // 64x65 masked QK^T
    float* dens = sm + 12480;     // 64
    float* kps  = dens + 64;      // 64

    int blk = blockIdx.x;
    int bh = blk / NCH, c = blk % NCH;
    int b = bh / HH, h = bh % HH;
    int tid = threadIdx.x;
    const float* Sc = S  + (bh * NCH + c) * 4096;
    const float* kc = ks + (bh * NCH + c) * 64;

    for (int i = tid; i < 4096; i += 256) {
        int t = i >> 6, d = i & 63;
        int row = b * LL + c * CHUNK + t;
        float qv = qkv[row * 768 + h * 64 + d];
        Qs[t * 65 + d] = fmaxf(qv, 0.f) + 1e-6f;
        Ts[t * 65 + d] = Sc[i];
    }
    if (tid < 64) kps[tid] = kc[tid];
    __syncthreads();

    int i0 = (tid >> 4) * 4, j0 = (tid & 15) * 4;
    float acc[4][4] = {};

    for (int d = 0; d < 64; d++) {
        float q[4], p[4];
#pragma unroll
        for (int i = 0; i < 4; i++) q[i] = Qs[(i0 + i) * 65 + d];
#pragma unroll
        for (int j = 0; j < 4; j++) p[j] = Ts[d * 65 + j0 + j];
#pragma unroll
        for (int i = 0; i < 4; i++)
#pragma unroll
            for (int j = 0; j < 4; j++)
                acc[i][j] += q[i] * p[j];
    }
    if (tid < 64) {
        float s = 0.f;
        for (int d = 0; d < 64; d++) s += Qs[tid * 65 + d] * kps[d];
        dens[tid] = s;
    }
    __syncthreads();

    for (int i = tid; i < 4096; i += 256) {
        int t = i >> 6, d = i & 63;
        int row = b * LL + c * CHUNK + t;
        float kv = qkv[row * 768 + 256 + h * 64 + d];
        Ts[t * 65 + d] = fmaxf(kv, 0.f) + 1e-6f;
    }
    __syncthreads();

    {
        float av[4][4] = {};
        for (int d = 0; d < 64; d++) {
            float q[4], kk[4];
#pragma unroll
            for (int i = 0; i < 4; i++) q[i]  = Qs[(i0 + i) * 65 + d];
#pragma unroll
            for (int j = 0; j < 4; j++) kk[j] = Ts[(j0 + j) * 65 + d];
#pragma unroll
            for (int i = 0; i < 4; i++)
#pragma unroll
                for (int j = 0; j < 4; j++)
                    av[i][j] += q[i] * kk[j];
        }
#pragma unroll
        for (int i = 0; i < 4; i++)
#pragma unroll
            for (int j = 0; j < 4; j++)
                As[(i0 + i) * 65 + (j0 + j)] = ((j0 + j) <= (i0 + i)) ? av[i][j] : 0.f;
    }
    __syncthreads();

    if (tid < 64) {
        float rs = 0.f;
        for (int j = 0; j < 64; j++) rs += As[tid * 65 + j];
        dens[tid] += rs;
    }
    for (int i = tid; i < 4096; i += 256) {
        int t = i >> 6, d = i & 63;
        int row = b * LL + c * CHUNK + t;
        Ts[t * 65 + d] = qkv[row * 768 + 512 + h * 64 + d];
    }
    __syncthreads();

    for (int j = 0; j < 64; j++) {
        float av[4], vv[4];
#pragma unroll
        for (int i = 0; i < 4; i++) av[i] = As[(i0 + i) * 65 + j];
#pragma unroll
        for (int jj = 0; jj < 4; jj++) vv[jj] = Ts[j * 65 + j0 + jj];
#pragma unroll
        for (int i = 0; i < 4; i++)
#pragma unroll
            for (int jj = 0; jj < 4; jj++)
                acc[i][jj] += av[i] * vv[jj];
    }
#pragma unroll
    for (int i = 0; i < 4; i++) {
        float dn = fmaxf(dens[i0 + i], 1e-6f);
        int row = b * LL + c * CHUNK + i0 + i;
        float inv = 1.0f / dn;
#pragma unroll
        for (int j = 0; j < 4; j++)
            o[row * EE + h * 64 + j0 + j] = acc[i][j] * inv;
    }
}

// ---------------- pred: state tokens @ pred_w + pred_b ---------------------
__global__ __launch_bounds__(256) void pred_kernel(
    const float* __restrict__ xn, const float* __restrict__ pred_w,
    const float* __restrict__ pred_b, float* __restrict__ out)
{
    int bk = blockIdx.x;
    int b = bk / KSTEP, k = bk % KSTEP;
    int row = b * LL + 3 * k + 1;
    __shared__ float xr[EE];
    int tid = threadIdx.x;
    xr[tid] = xn[row * EE + tid];
    __syncthreads();
    int w = tid >> 5, lane = tid & 31;
    if (w < NACT) {
        float s = 0.f;
        for (int e = lane; e < EE; e += 32) s += xr[e] * pred_w[e * NACT + w];
#pragma unroll
        for (int o = 16; o; o >>= 1) s += __shfl_xor_sync(0xffffffffu, s, o);
        if (lane == 0) out[bk * NACT + w] = s + pred_b[w];
    }
}

// ---------------- launch ----------------------------------------------------
extern "C" void kernel_launch(void* const* d_in, const int* in_sizes, int n_in,
                              void* d_out, int out_size)
{
    const float* rtg      = (const float*)d_in[0];
    const float* state    = (const float*)d_in[1];
    const float* action   = (const float*)d_in[2];
    const float* rtg_w    = (const float*)d_in[3];
    const float* rtg_b    = (const float*)d_in[4];
    const float* state_w  = (const float*)d_in[5];
    const float* state_b  = (const float*)d_in[6];
    const float* action_w = (const float*)d_in[7];
    const float* action_b = (const float*)d_in[8];
    const float* pos_emb  = (const float*)d_in[9];
    const float* norm1_g  = (const float*)d_in[10];
    const float* norm1_b  = (const float*)d_in[11];
    const float* qkv_w    = (const float*)d_in[12];
    const float* qkv_b    = (const float*)d_in[13];
    const float* out_w    = (const float*)d_in[14];
    const float* out_b    = (const float*)d_in[15];
    const float* norm2_g  = (const float*)d_in[16];
    const float* norm2_b  = (const float*)d_in[17];
    const float* ffn1_w   = (const float*)d_in[18];
    const float* ffn1_b   = (const float*)d_in[19];
    const float* ffn2_w   = (const float*)d_in[20];
    const float* ffn2_b   = (const float*)d_in[21];
    const float* normf_g  = (const float*)d_in[22];
    const float* normf_b  = (const float*)d_in[23];
    const float* pred_w   = (const float*)d_in[24];
    const float* pred_b   = (const float*)d_in[25];

    float *x, *xn, *qkv, *o, *ff, *sp, *S, *ks;
    cudaGetSymbolAddress((void**)&x,   g_x);
    cudaGetSymbolAddress((void**)&xn,  g_xn);
    cudaGetSymbolAddress((void**)&qkv, g_qkv);
    cudaGetSymbolAddress((void**)&o,   g_o);
    cudaGetSymbolAddress((void**)&ff,  g_ff);
    cudaGetSymbolAddress((void**)&sp,  g_sp);
    cudaGetSymbolAddress((void**)&S,   g_S);
    cudaGetSymbolAddress((void**)&ks,  g_ks);

    const int SMEM_C = (4160 * 3 + 128) * sizeof(float);
    cudaFuncSetAttribute(attn_out_kernel,
                         cudaFuncAttributeMaxDynamicSharedMemorySize, SMEM_C);

    embed_kernel<<<MTOK, 256>>>(rtg, state, action, rtg_w, rtg_b, state_w, state_b,
                                action_w, action_b, pos_emb, x);

    for (int layer = 0; layer < NLAYER; layer++) {
        const float* n1g = norm1_g + layer * EE;
        const float* n1b = norm1_b + layer * EE;
        const float* n2g = norm2_g + layer * EE;
        const float* n2b = norm2_b + layer * EE;
        const float* qw  = qkv_w  + layer * EE * 3 * EE;
        const float* qb  = qkv_b  + layer * 3 * EE;
        const float* ow  = out_w  + layer * EE * EE;
        const float* ob  = out_b  + layer * EE;
        const float* f1w = ffn1_w + layer * EE * FFD;
        const float* f1b = ffn1_b + layer * FFD;
        const float* f2w = ffn2_w + layer * FFD * EE;
        const float* f2b = ffn2_b + layer * EE;

        ln_kernel<<<MTOK, 256>>>(x, n1g, n1b, xn);

        // qkv: [3072,256] @ [256,768]
        gemm128_kernel<0><<<dim3(768 / 128, MTOK / 128, 1), 256>>>(
            xn, qw, qb, qkv, MTOK, 768, EE);

        attn_chunksum_kernel<<<NBH * NCH, 256>>>(qkv, S, ks);
        attn_scan_kernel<<<NBH, 256>>>(S, ks);
        attn_out_kernel<<<NBH * NCH, 256, SMEM_C>>>(qkv, S, ks, o);

        // out proj: [3072,256] @ [256,256], split-K=2, then reduce(+bias+res)
        gemm128_kernel<3><<<dim3(EE / 128, MTOK / 128, 2), 256>>>(
            o, ow, nullptr, sp, MTOK, EE, EE);
        reduce_kernel<2><<<MTOK * EE / 1024, 256>>>(sp, ob, x, x);

        ln_kernel<<<MTOK, 256>>>(x, n2g, n2b, xn);

        // ffn1: [3072,256] @ [256,1024] + GELU
        gemm128_kernel<1><<<dim3(FFD / 128, MTOK / 128, 1), 256>>>(
            xn, f1w, f1b, ff, MTOK, FFD, EE);

        // ffn2: [3072,1024] @ [1024,256], split-K=4, then reduce(+bias+res)
        gemm128_kernel<3><<<dim3(EE / 128, MTOK / 128, 4), 256>>>(
            ff, f2w, nullptr, sp, MTOK, EE, FFD);
        reduce_kernel<4><<<MTOK * EE / 1024, 256>>>(sp, f2b, x, x);
    }

    ln_kernel<<<MTOK, 256>>>(x, normf_g, normf_b, xn);
    pred_kernel<<<BB * KSTEP, 256>>>(xn, pred_w, pred_b, (float*)d_out);
}

// round 4
// speedup vs baseline: 1.8154x; 1.4180x over previous
#include <cuda_runtime.h>
#include <cuda_bf16.h>
#include <math.h>
#include <stdint.h>

#define BB     2
#define KSTEP  512
#define SDIM   60
#define NACT   5
#define EE     256
#define HH     4
#define DD     64
#define FFD    1024
#define NLAYER 2
#define LL     1536          // 3*KSTEP
#define MTOK   3072          // BB*LL
#define CHUNK  64
#define NCH    24            // LL/CHUNK
#define NBH    8             // BB*HH

#define WTOT   1572864       // total split-weight elements (bf16)

// ---------------- scratch (device globals; no allocation) ----------------
__device__ float g_x  [MTOK * EE];
__device__ float g_xn [MTOK * EE];
__device__ float g_qkv[MTOK * 3 * EE];
__device__ float g_S  [NBH * NCH * DD * DD];
__device__ float g_ks [NBH * NCH * DD];
__device__ __nv_bfloat16 g_xh [MTOK * EE];
__device__ __nv_bfloat16 g_xl [MTOK * EE];
__device__ __nv_bfloat16 g_oh [MTOK * EE];
__device__ __nv_bfloat16 g_ol [MTOK * EE];
__device__ __nv_bfloat16 g_ffh[MTOK * FFD];
__device__ __nv_bfloat16 g_ffl[MTOK * FFD];
__device__ __nv_bfloat16 g_wh [WTOT];
__device__ __nv_bfloat16 g_wl [WTOT];

// ---------------- helpers ----------------------------------------------------
__device__ __forceinline__ uint32_t smem_u32(const void* p) {
    uint32_t a;
    asm("{ .reg .u64 t; cvta.to.shared.u64 t, %1; cvt.u32.u64 %0, t; }" : "=r"(a) : "l"(p));
    return a;
}
__device__ __forceinline__ void cp_async16(uint32_t dst, const void* src) {
    asm volatile("cp.async.cg.shared.global [%0], [%1], 16;" :: "r"(dst), "l"(src) : "memory");
}
__device__ __forceinline__ void cp_commit() { asm volatile("cp.async.commit_group;" ::: "memory"); }

__device__ __forceinline__ void ldsm_x4(uint32_t* r, uint32_t addr) {
    asm volatile("ldmatrix.sync.aligned.m8n8.x4.shared.b16 {%0,%1,%2,%3}, [%4];"
                 : "=r"(r[0]), "=r"(r[1]), "=r"(r[2]), "=r"(r[3]) : "r"(addr));
}
__device__ __forceinline__ void mma_bf16(float* c, const uint32_t* a, const uint32_t* b) {
    asm volatile(
        "mma.sync.aligned.m16n8k16.row.col.f32.bf16.bf16.f32 "
        "{%0,%1,%2,%3}, {%4,%5,%6,%7}, {%8,%9}, {%0,%1,%2,%3};"
        : "+f"(c[0]), "+f"(c[1]), "+f"(c[2]), "+f"(c[3])
        : "r"(a[0]), "r"(a[1]), "r"(a[2]), "r"(a[3]), "r"(b[0]), "r"(b[1]));
}

__device__ __forceinline__ float gelu_exact(float x) {
    return 0.5f * x * (1.0f + erff(x * 0.70710678118654752f));
}

// ---------------- weight transpose + bf16 split -----------------------------
// W[K,N] fp32 -> Wh,Wl [N,K] bf16 (8 matrices via blockIdx.z)
__global__ __launch_bounds__(256) void wsplit_kernel(
    const float* __restrict__ qkv_w, const float* __restrict__ out_w,
    const float* __restrict__ f1w, const float* __restrict__ f2w,
    __nv_bfloat16* __restrict__ Wh, __nv_bfloat16* __restrict__ Wl)
{
    const float* src; int Kd, Nd; size_t doff;
    switch (blockIdx.z) {
        case 0: src = qkv_w;          Kd = 256;  Nd = 768;  doff = 0;       break;
        case 1: src = qkv_w + 196608; Kd = 256;  Nd = 768;  doff = 196608;  break;
        case 2: src = out_w;          Kd = 256;  Nd = 256;  doff = 393216;  break;
        case 3: src = out_w + 65536;  Kd = 256;  Nd = 256;  doff = 458752;  break;
        case 4: src = f1w;            Kd = 256;  Nd = 1024; doff = 524288;  break;
        case 5: src = f1w + 262144;   Kd = 256;  Nd = 1024; doff = 786432;  break;
        case 6: src = f2w;            Kd = 1024; Nd = 256;  doff = 1048576; break;
        default:src = f2w + 262144;   Kd = 1024; Nd = 256;  doff = 1310720; break;
    }
    int nt = blockIdx.x * 32, kt = blockIdx.y * 32;
    if (nt >= Nd || kt >= Kd) return;
    __shared__ float t[32][33];
#pragma unroll
    for (int i = 0; i < 4; i++) {
        int r = kt + threadIdx.y + i * 8;
        t[threadIdx.y + i * 8][threadIdx.x] = src[(size_t)r * Nd + nt + threadIdx.x];
    }
    __syncthreads();
#pragma unroll
    for (int i = 0; i < 4; i++) {
        int n = nt + threadIdx.y + i * 8;
        int k = kt + threadIdx.x;
        float v = t[threadIdx.x][threadIdx.y + i * 8];
        __nv_bfloat16 h = __float2bfloat16(v);
        Wh[doff + (size_t)n * Kd + k] = h;
        Wl[doff + (size_t)n * Kd + k] = __float2bfloat16(v - __bfloat162float(h));
    }
}

// ---------------- embed ------------------------------------------------------
__global__ __launch_bounds__(256) void embed_kernel(
    const float* __restrict__ rtg, const float* __restrict__ state,
    const float* __restrict__ action,
    const float* __restrict__ rtg_w, const float* __restrict__ rtg_b,
    const float* __restrict__ state_w, const float* __restrict__ state_b,
    const float* __restrict__ action_w, const float* __restrict__ action_b,
    const float* __restrict__ pos, float* __restrict__ x)
{
    int tok = blockIdx.x;
    int e   = threadIdx.x;
    int b   = tok / LL;
    int l   = tok % LL;
    int k   = l / 3;
    int typ = l % 3;
    float acc = pos[k * EE + e];
    if (typ == 0) {
        acc += rtg[b * KSTEP + k] * rtg_w[e] + rtg_b[e];
    } else if (typ == 1) {
        const float* s = state + (b * KSTEP + k) * SDIM;
        float sum = 0.f;
        for (int i = 0; i < SDIM; i++) sum += s[i] * state_w[i * EE + e];
        acc += sum + state_b[e];
    } else {
        const float* a = action + (b * KSTEP + k) * NACT;
        float sum = 0.f;
#pragma unroll
        for (int i = 0; i < NACT; i++) sum += a[i] * action_w[i * EE + e];
        acc += sum + action_b[e];
    }
    x[tok * EE + e] = acc;
}

// ---------------- LayerNorm (writes fp32 + bf16 hi/lo) ----------------------
__global__ __launch_bounds__(256) void ln_kernel(
    const float* __restrict__ x, const float* __restrict__ g,
    const float* __restrict__ bta, float* __restrict__ y,
    __nv_bfloat16* __restrict__ yh, __nv_bfloat16* __restrict__ yl)
{
    int row = blockIdx.x;
    int e   = threadIdx.x;
    __shared__ float red[8];
    float v = x[row * EE + e];

    float s = v;
#pragma unroll
    for (int o = 16; o; o >>= 1) s += __shfl_xor_sync(0xffffffffu, s, o);
    if ((e & 31) == 0) red[e >> 5] = s;
    __syncthreads();
    if (e < 8) {
        float t = red[e];
#pragma unroll
        for (int o = 4; o; o >>= 1) t += __shfl_xor_sync(0xffu, t, o);
        if (e == 0) red[0] = t;
    }
    __syncthreads();
    float mean = red[0] * (1.0f / EE);
    __syncthreads();

    float d  = v - mean;
    float s2 = d * d;
#pragma unroll
    for (int o = 16; o; o >>= 1) s2 += __shfl_xor_sync(0xffffffffu, s2, o);
    if ((e & 31) == 0) red[e >> 5] = s2;
    __syncthreads();
    if (e < 8) {
        float t = red[e];
#pragma unroll
        for (int o = 4; o; o >>= 1) t += __shfl_xor_sync(0xffu, t, o);
        if (e == 0) red[0] = t;
    }
    __syncthreads();
    float var = red[0] * (1.0f / EE);
    float r = rsqrtf(var + 1e-5f);
    float yv = d * r * g[e] + bta[e];
    y[row * EE + e] = yv;
    __nv_bfloat16 h = __float2bfloat16(yv);
    yh[row * EE + e] = h;
    yl[row * EE + e] = __float2bfloat16(yv - __bfloat162float(h));
}

// ---------------- HMMA GEMM: 128x64 block tile, bf16-split fp32 -------------
// A (hi/lo): [M,K] bf16 row-major. B (hi/lo): [N,K] bf16 row-major.
// EPI: 0 = +bias -> fp32 Cf; 1 = gelu(+bias) -> bf16 Ch/Cl; 2 = +bias+Res -> fp32 Cf
template <int EPI>
__global__ __launch_bounds__(256) void gemm_mma_kernel(
    const __nv_bfloat16* __restrict__ Ah, const __nv_bfloat16* __restrict__ Al,
    const __nv_bfloat16* __restrict__ Bh, const __nv_bfloat16* __restrict__ Bl,
    const float* __restrict__ bias, const float* Res,
    float* Cf, __nv_bfloat16* Ch, __nv_bfloat16* Cl,
    int N, int K)
{
    extern __shared__ char smem[];
    constexpr int RS = 40;                 // padded row stride (elems)
    constexpr int A_BYTES = 128 * RS * 2;  // 10240
    constexpr int B_BYTES = 64 * RS * 2;   // 5120
    constexpr int OFF_AL = A_BYTES;
    constexpr int OFF_BH = 2 * A_BYTES;
    constexpr int SS = 2 * A_BYTES + 2 * B_BYTES;  // 30720 per stage

    uint32_t sb = smem_u32(smem);
    const int tid = threadIdx.x;
    const int m0 = blockIdx.y * 128, n0 = blockIdx.x * 64;

    const int lane = tid & 31, wid = tid >> 5;
    const int wm = (wid >> 1) * 32;        // 0,32,64,96
    const int wn = (wid & 1) * 32;         // 0,32
    const int lr = lane & 15, lc = lane >> 4;

    float acc[2][4][4] = {};

    auto load_stage = [&](int buf, int k0) {
        uint32_t st = sb + buf * SS;
#pragma unroll
        for (int i = 0; i < 2; i++) {
            int u = tid + i * 256;         // 0..511
            int r = u >> 2, c = u & 3;
            uint32_t d = st + (uint32_t)(r * RS + c * 8) * 2;
            cp_async16(d,          Ah + (size_t)(m0 + r) * K + k0 + c * 8);
            cp_async16(d + OFF_AL, Al + (size_t)(m0 + r) * K + k0 + c * 8);
        }
        {
            int r = tid >> 2, c = tid & 3; // 64 rows x 4 chunks
            uint32_t d = st + OFF_BH + (uint32_t)(r * RS + c * 8) * 2;
            cp_async16(d,           Bh + (size_t)(n0 + r) * K + k0 + c * 8);
            cp_async16(d + B_BYTES, Bl + (size_t)(n0 + r) * K + k0 + c * 8);
        }
    };

    load_stage(0, 0);
    cp_commit();

    const int NST = K >> 5;                // BK = 32
    for (int s = 0; s < NST; s++) {
        if (s + 1 < NST) { load_stage((s + 1) & 1, (s + 1) << 5); cp_commit(); }
        if (s + 1 < NST) asm volatile("cp.async.wait_group 1;" ::: "memory");
        else             asm volatile("cp.async.wait_group 0;" ::: "memory");
        __syncthreads();

        uint32_t st = sb + (s & 1) * SS;
#pragma unroll
        for (int kk = 0; kk < 2; kk++) {
            uint32_t ah[2][4], al[2][4], bh[2][4], bl[2][4];
#pragma unroll
            for (int mt = 0; mt < 2; mt++) {
                uint32_t ad = st + (uint32_t)((wm + mt * 16 + lr) * RS + kk * 16 + lc * 8) * 2;
                ldsm_x4(ah[mt], ad);
                ldsm_x4(al[mt], ad + OFF_AL);
            }
#pragma unroll
            for (int np = 0; np < 2; np++) {
                uint32_t bd = st + OFF_BH + (uint32_t)((wn + np * 16 + lr) * RS + kk * 16 + lc * 8) * 2;
                ldsm_x4(bh[np], bd);
                ldsm_x4(bl[np], bd + B_BYTES);
            }
#pragma unroll
            for (int mt = 0; mt < 2; mt++)
#pragma unroll
                for (int nt = 0; nt < 4; nt++) {
                    uint32_t bhp[2] = { bh[nt >> 1][nt & 1], bh[nt >> 1][2 + (nt & 1)] };
                    uint32_t blp[2] = { bl[nt >> 1][nt & 1], bl[nt >> 1][2 + (nt & 1)] };
                    mma_bf16(acc[mt][nt], ah[mt], bhp);
                    mma_bf16(acc[mt][nt], ah[mt], blp);
                    mma_bf16(acc[mt][nt], al[mt], bhp);
                }
        }
        __syncthreads();
    }

    // ---------------- epilogue -------------------------------------------
    const int tr = lane >> 2;          // 0..7
    const int tc = (lane & 3) * 2;     // 0,2,4,6
#pragma unroll
    for (int mt = 0; mt < 2; mt++) {
#pragma unroll
        for (int nt = 0; nt < 4; nt++) {
            int col = n0 + wn + nt * 8 + tc;
            float b0 = bias[col], b1 = bias[col + 1];
#pragma unroll
            for (int half = 0; half < 2; half++) {
                int row = m0 + wm + mt * 16 + tr + half * 8;
                float v0 = acc[mt][nt][half * 2]     + b0;
                float v1 = acc[mt][nt][half * 2 + 1] + b1;
                if (EPI == 1) {
                    v0 = gelu_exact(v0);
                    v1 = gelu_exact(v1);
                    __nv_bfloat16 h0 = __float2bfloat16(v0);
                    __nv_bfloat16 h1 = __float2bfloat16(v1);
                    __nv_bfloat162 hp; hp.x = h0; hp.y = h1;
                    __nv_bfloat162 lp;
                    lp.x = __float2bfloat16(v0 - __bfloat162float(h0));
                    lp.y = __float2bfloat16(v1 - __bfloat162float(h1));
                    *(__nv_bfloat162*)&Ch[(size_t)row * N + col] = hp;
                    *(__nv_bfloat162*)&Cl[(size_t)row * N + col] = lp;
                } else {
                    if (EPI == 2) {
                        float2 rv = *(const float2*)&Res[(size_t)row * N + col];
                        v0 += rv.x; v1 += rv.y;
                    }
                    float2 ov; ov.x = v0; ov.y = v1;
                    *(float2*)&Cf[(size_t)row * N + col] = ov;
                }
            }
        }
    }
}

// ---------------- attention pass A: per-chunk sums --------------------------
__global__ __launch_bounds__(256) void attn_chunksum_kernel(
    const float* __restrict__ qkv, float* __restrict__ S, float* __restrict__ ks)
{
    __shared__ float Ks[64 * 65];
    __shared__ float Vs[64 * 65];
    int blk = blockIdx.x;
    int bh = blk / NCH, c = blk % NCH;
    int b = bh / HH, h = bh % HH;
    int tid = threadIdx.x;

    for (int i = tid; i < 4096; i += 256) {
        int t = i >> 6, d = i & 63;
        int row = b * LL + c * CHUNK + t;
        float kv = qkv[row * 768 + 256 + h * 64 + d];
        Ks[t * 65 + d] = fmaxf(kv, 0.f) + 1e-6f;
        Vs[t * 65 + d] = qkv[row * 768 + 512 + h * 64 + d];
    }
    __syncthreads();

    int d0 = (tid >> 4) * 4, e0 = (tid & 15) * 4;
    float acc[4][4] = {};
    for (int t = 0; t < 64; t++) {
        float kd[4], ve[4];
#pragma unroll
        for (int i = 0; i < 4; i++) kd[i] = Ks[t * 65 + d0 + i];
#pragma unroll
        for (int j = 0; j < 4; j++) ve[j] = Vs[t * 65 + e0 + j];
#pragma unroll
        for (int i = 0; i < 4; i++)
#pragma unroll
            for (int j = 0; j < 4; j++)
                acc[i][j] += kd[i] * ve[j];
    }
    float* So = S + (bh * NCH + c) * 4096;
#pragma unroll
    for (int i = 0; i < 4; i++)
#pragma unroll
        for (int j = 0; j < 4; j++)
            So[(d0 + i) * 64 + e0 + j] = acc[i][j];

    if (tid < 64) {
        float s = 0.f;
        for (int t = 0; t < 64; t++) s += Ks[t * 65 + tid];
        ks[(bh * NCH + c) * 64 + tid] = s;
    }
}

// ---------------- attention pass B: exclusive prefix over chunks -----------
__global__ __launch_bounds__(256) void attn_scan_kernel(
    float* __restrict__ S, float* __restrict__ ks)
{
    int bh = blockIdx.x;
    int tid = threadIdx.x;
    for (int e = tid; e < 4096; e += 256) {
        float carry = 0.f;
        for (int c = 0; c < NCH; c++) {
            float* p = &S[(bh * NCH + c) * 4096 + e];
            float t = *p; *p = carry; carry += t;
        }
    }
    if (tid < 64) {
        float carry = 0.f;
        for (int c = 0; c < NCH; c++) {
            float* p = &ks[(bh * NCH + c) * 64 + tid];
            float t = *p; *p = carry; carry += t;
        }
    }
}

// ---------------- attention pass C: per-chunk output (writes bf16 hi/lo) ---
__global__ __launch_bounds__(256) void attn_out_kernel(
    const float* __restrict__ qkv, const float* __restrict__ S,
    const float* __restrict__ ks,
    __nv_bfloat16* __restrict__ oh, __nv_bfloat16* __restrict__ ol)
{
    extern __shared__ float sm[];
    float* Qs   = sm;             // 64x65 (relu(q)+eps)
    float* Ts   = sm + 4160;      // 64x65 temp: P, then K, then V
    float* As   = sm + 8320;      // 64x65 masked QK^T
    float* dens = sm + 12480;     // 64
    float* kps  = dens + 64;      // 64

    int blk = blockIdx.x;
    int bh = blk / NCH, c = blk % NCH;
    int b = bh / HH, h = bh % HH;
    int tid = threadIdx.x;
    const float* Sc = S  + (bh * NCH + c) * 4096;
    const float* kc = ks + (bh * NCH + c) * 64;

    for (int i = tid; i < 4096; i += 256) {
        int t = i >> 6, d = i & 63;
        int row = b * LL + c * CHUNK + t;
        float qv = qkv[row * 768 + h * 64 + d];
        Qs[t * 65 + d] = fmaxf(qv, 0.f) + 1e-6f;
        Ts[t * 65 + d] = Sc[i];
    }
    if (tid < 64) kps[tid] = kc[tid];
    __syncthreads();

    int i0 = (tid >> 4) * 4, j0 = (tid & 15) * 4;
    float acc[4][4] = {};

    for (int d = 0; d < 64; d++) {
        float q[4], p[4];
#pragma unroll
        for (int i = 0; i < 4; i++) q[i] = Qs[(i0 + i) * 65 + d];
#pragma unroll
        for (int j = 0; j < 4; j++) p[j] = Ts[d * 65 + j0 + j];
#pragma unroll
        for (int i = 0; i < 4; i++)
#pragma unroll
            for (int j = 0; j < 4; j++)
                acc[i][j] += q[i] * p[j];
    }
    if (tid < 64) {
        float s = 0.f;
        for (int d = 0; d < 64; d++) s += Qs[tid * 65 + d] * kps[d];
        dens[tid] = s;
    }
    __syncthreads();

    for (int i = tid; i < 4096; i += 256) {
        int t = i >> 6, d = i & 63;
        int row = b * LL + c * CHUNK + t;
        float kv = qkv[row * 768 + 256 + h * 64 + d];
        Ts[t * 65 + d] = fmaxf(kv, 0.f) + 1e-6f;
    }
    __syncthreads();

    {
        float av[4][4] = {};
        for (int d = 0; d < 64; d++) {
            float q[4], kk[4];
#pragma unroll
            for (int i = 0; i < 4; i++) q[i]  = Qs[(i0 + i) * 65 + d];
#pragma unroll
            for (int j = 0; j < 4; j++) kk[j] = Ts[(j0 + j) * 65 + d];
#pragma unroll
            for (int i = 0; i < 4; i++)
#pragma unroll
                for (int j = 0; j < 4; j++)
                    av[i][j] += q[i] * kk[j];
        }
#pragma unroll
        for (int i = 0; i < 4; i++)
#pragma unroll
            for (int j = 0; j < 4; j++)
                As[(i0 + i) * 65 + (j0 + j)] = ((j0 + j) <= (i0 + i)) ? av[i][j] : 0.f;
    }
    __syncthreads();

    if (tid < 64) {
        float rs = 0.f;
        for (int j = 0; j < 64; j++) rs += As[tid * 65 + j];
        dens[tid] += rs;
    }
    for (int i = tid; i < 4096; i += 256) {
        int t = i >> 6, d = i & 63;
        int row = b * LL + c * CHUNK + t;
        Ts[t * 65 + d] = qkv[row * 768 + 512 + h * 64 + d];
    }
    __syncthreads();

    for (int j = 0; j < 64; j++) {
        float av[4], vv[4];
#pragma unroll
        for (int i = 0; i < 4; i++) av[i] = As[(i0 + i) * 65 + j];
#pragma unroll
        for (int jj = 0; jj < 4; jj++) vv[jj] = Ts[j * 65 + j0 + jj];
#pragma unroll
        for (int i = 0; i < 4; i++)
#pragma unroll
            for (int jj = 0; jj < 4; jj++)
                acc[i][jj] += av[i] * vv[jj];
    }
#pragma unroll
    for (int i = 0; i < 4; i++) {
        float dn = fmaxf(dens[i0 + i], 1e-6f);
        int row = b * LL + c * CHUNK + i0 + i;
        float inv = 1.0f / dn;
#pragma unroll
        for (int j = 0; j < 4; j++) {
            float v = acc[i][j] * inv;
            __nv_bfloat16 hh = __float2bfloat16(v);
            size_t idx = (size_t)row * EE + h * 64 + j0 + j;
            oh[idx] = hh;
            ol[idx] = __float2bfloat16(v - __bfloat162float(hh));
        }
    }
}

// ---------------- pred: state tokens @ pred_w + pred_b ---------------------
__global__ __launch_bounds__(256) void pred_kernel(
    const float* __restrict__ xn, const float* __restrict__ pred_w,
    const float* __restrict__ pred_b, float* __restrict__ out)
{
    int bk = blockIdx.x;
    int b = bk / KSTEP, k = bk % KSTEP;
    int row = b * LL + 3 * k + 1;
    __shared__ float xr[EE];
    int tid = threadIdx.x;
    xr[tid] = xn[row * EE + tid];
    __syncthreads();
    int w = tid >> 5, lane = tid & 31;
    if (w < NACT) {
        float s = 0.f;
        for (int e = lane; e < EE; e += 32) s += xr[e] * pred_w[e * NACT + w];
#pragma unroll
        for (int o = 16; o; o >>= 1) s += __shfl_xor_sync(0xffffffffu, s, o);
        if (lane == 0) out[bk * NACT + w] = s + pred_b[w];
    }
}

// ---------------- launch ----------------------------------------------------
extern "C" void kernel_launch(void* const* d_in, const int* in_sizes, int n_in,
                              void* d_out, int out_size)
{
    const float* rtg      = (const float*)d_in[0];
    const float* state    = (const float*)d_in[1];
    const float* action   = (const float*)d_in[2];
    const float* rtg_w    = (const float*)d_in[3];
    const float* rtg_b    = (const float*)d_in[4];
    const float* state_w  = (const float*)d_in[5];
    const float* state_b  = (const float*)d_in[6];
    const float* action_w = (const float*)d_in[7];
    const float* action_b = (const float*)d_in[8];
    const float* pos_emb  = (const float*)d_in[9];
    const float* norm1_g  = (const float*)d_in[10];
    const float* norm1_b  = (const float*)d_in[11];
    const float* qkv_w    = (const float*)d_in[12];
    const float* qkv_b    = (const float*)d_in[13];
    const float* out_w    = (const float*)d_in[14];
    const float* out_b    = (const float*)d_in[15];
    const float* norm2_g  = (const float*)d_in[16];
    const float* norm2_b  = (const float*)d_in[17];
    const float* ffn1_w   = (const float*)d_in[18];
    const float* ffn1_b   = (const float*)d_in[19];
    const float* ffn2_w   = (const float*)d_in[20];
    const float* ffn2_b   = (const float*)d_in[21];
    const float* normf_g  = (const float*)d_in[22];
    const float* normf_b  = (const float*)d_in[23];
    const float* pred_w   = (const float*)d_in[24];
    const float* pred_b   = (const float*)d_in[25];

    float *x, *xn, *qkv, *S, *ks;
    __nv_bfloat16 *xh, *xl, *oh, *ol, *ffh, *ffl, *wh, *wl;
    cudaGetSymbolAddress((void**)&x,   g_x);
    cudaGetSymbolAddress((void**)&xn,  g_xn);
    cudaGetSymbolAddress((void**)&qkv, g_qkv);
    cudaGetSymbolAddress((void**)&S,   g_S);
    cudaGetSymbolAddress((void**)&ks,  g_ks);
    cudaGetSymbolAddress((void**)&xh,  g_xh);
    cudaGetSymbolAddress((void**)&xl,  g_xl);
    cudaGetSymbolAddress((void**)&oh,  g_oh);
    cudaGetSymbolAddress((void**)&ol,  g_ol);
    cudaGetSymbolAddress((void**)&ffh, g_ffh);
    cudaGetSymbolAddress((void**)&ffl, g_ffl);
    cudaGetSymbolAddress((void**)&wh,  g_wh);
    cudaGetSymbolAddress((void**)&wl,  g_wl);

    const int SMEM_C = (4160 * 3 + 128) * sizeof(float);   // attn_out
    const int SMEM_G = 61440;                              // 2 stages x 30720
    cudaFuncSetAttribute(attn_out_kernel,
                         cudaFuncAttributeMaxDynamicSharedMemorySize, SMEM_C);
    cudaFuncSetAttribute((const void*)gemm_mma_kernel<0>,
                         cudaFuncAttributeMaxDynamicSharedMemorySize, SMEM_G);
    cudaFuncSetAttribute((const void*)gemm_mma_kernel<1>,
                         cudaFuncAttributeMaxDynamicSharedMemorySize, SMEM_G);
    cudaFuncSetAttribute((const void*)gemm_mma_kernel<2>,
                         cudaFuncAttributeMaxDynamicSharedMemorySize, SMEM_G);

    // weights -> transposed bf16 hi/lo (once per launch)
    wsplit_kernel<<<dim3(32, 32, 8), dim3(32, 8)>>>(qkv_w, out_w, ffn1_w, ffn2_w, wh, wl);

    embed_kernel<<<MTOK, 256>>>(rtg, state, action, rtg_w, rtg_b, state_w, state_b,
                                action_w, action_b, pos_emb, x);

    for (int layer = 0; layer < NLAYER; layer++) {
        const float* n1g = norm1_g + layer * EE;
        const float* n1b = norm1_b + layer * EE;
        const float* n2g = norm2_g + layer * EE;
        const float* n2b = norm2_b + layer * EE;
        const float* qb  = qkv_b  + layer * 3 * EE;
        const float* ob  = out_b  + layer * EE;
        const float* f1b = ffn1_b + layer * FFD;
        const float* f2b = ffn2_b + layer * EE;
        size_t qoff  = (size_t)layer * 196608;
        size_t ooff  = 393216  + (size_t)layer * 65536;
        size_t f1off = 524288  + (size_t)layer * 262144;
        size_t f2off = 1048576 + (size_t)layer * 262144;

        ln_kernel<<<MTOK, 256>>>(x, n1g, n1b, xn, xh, xl);

        // qkv: [3072,256] @ [256,768]
        gemm_mma_kernel<0><<<dim3(12, 24), 256, SMEM_G>>>(
            xh, xl, wh + qoff, wl + qoff, qb, nullptr, qkv, nullptr, nullptr, 768, 256);

        attn_chunksum_kernel<<<NBH * NCH, 256>>>(qkv, S, ks);
        attn_scan_kernel<<<NBH, 256>>>(S, ks);
        attn_out_kernel<<<NBH * NCH, 256, SMEM_C>>>(qkv, S, ks, oh, ol);

        // out proj: [3072,256] @ [256,256] + bias + residual
        gemm_mma_kernel<2><<<dim3(4, 24), 256, SMEM_G>>>(
            oh, ol, wh + ooff, wl + ooff, ob, x, x, nullptr, nullptr, 256, 256);

        ln_kernel<<<MTOK, 256>>>(x, n2g, n2b, xn, xh, xl);

        // ffn1: [3072,256] @ [256,1024] + bias + GELU -> bf16 hi/lo
        gemm_mma_kernel<1><<<dim3(16, 24), 256, SMEM_G>>>(
            xh, xl, wh + f1off, wl + f1off, f1b, nullptr, nullptr, ffh, ffl, 1024, 256);

        // ffn2: [3072,1024] @ [1024,256] + bias + residual
        gemm_mma_kernel<2><<<dim3(4, 24), 256, SMEM_G>>>(
            ffh, ffl, wh + f2off, wl + f2off, f2b, x, x, nullptr, nullptr, 256, 1024);
    }

    ln_kernel<<<MTOK, 256>>>(x, normf_g, normf_b, xn, xh, xl);
    pred_kernel<<<BB * KSTEP, 256>>>(xn, pred_w, pred_b, (float*)d_out);
}

// round 5
// speedup vs baseline: 2.3742x; 1.3078x over previous
#include <cuda_runtime.h>
#include <cuda_bf16.h>
#include <math.h>
#include <stdint.h>

#define BB     2
#define KSTEP  512
#define SDIM   60
#define NACT   5
#define EE     256
#define HH     4
#define DD     64
#define FFD    1024
#define NLAYER 2
#define LL     1536          // 3*KSTEP
#define MTOK   3072          // BB*LL
#define CHUNK  64
#define NCH    24            // LL/CHUNK
#define NBH    8             // BB*HH

#define WTOT   1572864       // total split-weight elements (bf16)

// ---------------- scratch (device globals; no allocation) ----------------
__device__ float g_x  [MTOK * EE];
__device__ float g_xn [MTOK * EE];
__device__ float g_qkv[MTOK * 3 * EE];
__device__ float g_S  [NBH * NCH * DD * DD];
__device__ float g_ks [NBH * NCH * DD];
__device__ __nv_bfloat16 g_xh [MTOK * EE];
__device__ __nv_bfloat16 g_xl [MTOK * EE];
__device__ __nv_bfloat16 g_oh [MTOK * EE];
__device__ __nv_bfloat16 g_ol [MTOK * EE];
__device__ __nv_bfloat16 g_ffh[MTOK * FFD];
__device__ __nv_bfloat16 g_ffl[MTOK * FFD];
__device__ __nv_bfloat16 g_wh [WTOT];
__device__ __nv_bfloat16 g_wl [WTOT];

// ---------------- helpers ----------------------------------------------------
__device__ __forceinline__ uint32_t smem_u32(const void* p) {
    uint32_t a;
    asm("{ .reg .u64 t; cvta.to.shared.u64 t, %1; cvt.u32.u64 %0, t; }" : "=r"(a) : "l"(p));
    return a;
}
__device__ __forceinline__ void cp_async16(uint32_t dst, const void* src) {
    asm volatile("cp.async.cg.shared.global [%0], [%1], 16;" :: "r"(dst), "l"(src) : "memory");
}
__device__ __forceinline__ void cp_commit() { asm volatile("cp.async.commit_group;" ::: "memory"); }

__device__ __forceinline__ void ldsm_x4(uint32_t* r, uint32_t addr) {
    asm volatile("ldmatrix.sync.aligned.m8n8.x4.shared.b16 {%0,%1,%2,%3}, [%4];"
                 : "=r"(r[0]), "=r"(r[1]), "=r"(r[2]), "=r"(r[3]) : "r"(addr));
}
__device__ __forceinline__ void mma_bf16(float* c, const uint32_t* a, const uint32_t* b) {
    asm volatile(
        "mma.sync.aligned.m16n8k16.row.col.f32.bf16.bf16.f32 "
        "{%0,%1,%2,%3}, {%4,%5,%6,%7}, {%8,%9}, {%0,%1,%2,%3};"
        : "+f"(c[0]), "+f"(c[1]), "+f"(c[2]), "+f"(c[3])
        : "r"(a[0]), "r"(a[1]), "r"(a[2]), "r"(a[3]), "r"(b[0]), "r"(b[1]));
}

__device__ __forceinline__ float gelu_exact(float x) {
    return 0.5f * x * (1.0f + erff(x * 0.70710678118654752f));
}

// ---------------- weight transpose + bf16 split -----------------------------
__global__ __launch_bounds__(256) void wsplit_kernel(
    const float* __restrict__ qkv_w, const float* __restrict__ out_w,
    const float* __restrict__ f1w, const float* __restrict__ f2w,
    __nv_bfloat16* __restrict__ Wh, __nv_bfloat16* __restrict__ Wl)
{
    const float* src; int Kd, Nd; size_t doff;
    switch (blockIdx.z) {
        case 0: src = qkv_w;          Kd = 256;  Nd = 768;  doff = 0;       break;
        case 1: src = qkv_w + 196608; Kd = 256;  Nd = 768;  doff = 196608;  break;
        case 2: src = out_w;          Kd = 256;  Nd = 256;  doff = 393216;  break;
        case 3: src = out_w + 65536;  Kd = 256;  Nd = 256;  doff = 458752;  break;
        case 4: src = f1w;            Kd = 256;  Nd = 1024; doff = 524288;  break;
        case 5: src = f1w + 262144;   Kd = 256;  Nd = 1024; doff = 786432;  break;
        case 6: src = f2w;            Kd = 1024; Nd = 256;  doff = 1048576; break;
        default:src = f2w + 262144;   Kd = 1024; Nd = 256;  doff = 1310720; break;
    }
    int nt = blockIdx.x * 32, kt = blockIdx.y * 32;
    if (nt >= Nd || kt >= Kd) return;
    __shared__ float t[32][33];
#pragma unroll
    for (int i = 0; i < 4; i++) {
        int r = kt + threadIdx.y + i * 8;
        t[threadIdx.y + i * 8][threadIdx.x] = src[(size_t)r * Nd + nt + threadIdx.x];
    }
    __syncthreads();
#pragma unroll
    for (int i = 0; i < 4; i++) {
        int n = nt + threadIdx.y + i * 8;
        int k = kt + threadIdx.x;
        float v = t[threadIdx.x][threadIdx.y + i * 8];
        __nv_bfloat16 h = __float2bfloat16(v);
        Wh[doff + (size_t)n * Kd + k] = h;
        Wl[doff + (size_t)n * Kd + k] = __float2bfloat16(v - __bfloat162float(h));
    }
}

// ---------------- embed fused with layer-0 LN1 ------------------------------
__global__ __launch_bounds__(256) void embed_ln_kernel(
    const float* __restrict__ rtg, const float* __restrict__ state,
    const float* __restrict__ action,
    const float* __restrict__ rtg_w, const float* __restrict__ rtg_b,
    const float* __restrict__ state_w, const float* __restrict__ state_b,
    const float* __restrict__ action_w, const float* __restrict__ action_b,
    const float* __restrict__ pos,
    const float* __restrict__ g, const float* __restrict__ bta,
    float* __restrict__ x,
    __nv_bfloat16* __restrict__ yh, __nv_bfloat16* __restrict__ yl)
{
    int tok = blockIdx.x;
    int e   = threadIdx.x;
    int b   = tok / LL;
    int l   = tok % LL;
    int k   = l / 3;
    int typ = l % 3;
    float acc = pos[k * EE + e];
    if (typ == 0) {
        acc += rtg[b * KSTEP + k] * rtg_w[e] + rtg_b[e];
    } else if (typ == 1) {
        const float* s = state + (b * KSTEP + k) * SDIM;
        float sum = 0.f;
        for (int i = 0; i < SDIM; i++) sum += s[i] * state_w[i * EE + e];
        acc += sum + state_b[e];
    } else {
        const float* a = action + (b * KSTEP + k) * NACT;
        float sum = 0.f;
#pragma unroll
        for (int i = 0; i < NACT; i++) sum += a[i] * action_w[i * EE + e];
        acc += sum + action_b[e];
    }
    x[tok * EE + e] = acc;

    __shared__ float red[8];
    float s = acc;
#pragma unroll
    for (int o = 16; o; o >>= 1) s += __shfl_xor_sync(0xffffffffu, s, o);
    if ((e & 31) == 0) red[e >> 5] = s;
    __syncthreads();
    if (e < 8) {
        float t = red[e];
#pragma unroll
        for (int o = 4; o; o >>= 1) t += __shfl_xor_sync(0xffu, t, o);
        if (e == 0) red[0] = t;
    }
    __syncthreads();
    float mean = red[0] * (1.0f / EE);
    __syncthreads();
    float d  = acc - mean;
    float s2 = d * d;
#pragma unroll
    for (int o = 16; o; o >>= 1) s2 += __shfl_xor_sync(0xffffffffu, s2, o);
    if ((e & 31) == 0) red[e >> 5] = s2;
    __syncthreads();
    if (e < 8) {
        float t = red[e];
#pragma unroll
        for (int o = 4; o; o >>= 1) t += __shfl_xor_sync(0xffu, t, o);
        if (e == 0) red[0] = t;
    }
    __syncthreads();
    float var = red[0] * (1.0f / EE);
    float r = rsqrtf(var + 1e-5f);
    float yv = d * r * g[e] + bta[e];
    __nv_bfloat16 h = __float2bfloat16(yv);
    yh[tok * EE + e] = h;
    yl[tok * EE + e] = __float2bfloat16(yv - __bfloat162float(h));
}

// ---------------- LayerNorm: 4 rows/block, float4 ---------------------------
__global__ __launch_bounds__(256) void ln4_kernel(
    const float* __restrict__ x, const float* __restrict__ g,
    const float* __restrict__ bta, float* __restrict__ y,
    __nv_bfloat16* __restrict__ yh, __nv_bfloat16* __restrict__ yl)
{
    __shared__ float red[16];
    int tid = threadIdx.x;
    int r   = tid >> 6;           // row within block (0..3)
    int l64 = tid & 63;
    int w   = tid >> 5;           // warp 0..7 (row r owns warps 2r, 2r+1)
    int lane = tid & 31;
    int row = blockIdx.x * 4 + r;
    size_t base = (size_t)row * EE + l64 * 4;

    float4 v = *(const float4*)&x[base];
    float s = v.x + v.y + v.z + v.w;
#pragma unroll
    for (int o = 16; o; o >>= 1) s += __shfl_xor_sync(0xffffffffu, s, o);
    if (lane == 0) red[w] = s;
    __syncthreads();
    float mean = (red[2 * r] + red[2 * r + 1]) * (1.0f / EE);

    float4 d;
    d.x = v.x - mean; d.y = v.y - mean; d.z = v.z - mean; d.w = v.w - mean;
    float s2 = d.x * d.x + d.y * d.y + d.z * d.z + d.w * d.w;
#pragma unroll
    for (int o = 16; o; o >>= 1) s2 += __shfl_xor_sync(0xffffffffu, s2, o);
    if (lane == 0) red[8 + w] = s2;
    __syncthreads();
    float var = (red[8 + 2 * r] + red[8 + 2 * r + 1]) * (1.0f / EE);
    float rs = rsqrtf(var + 1e-5f);

    float4 gv = *(const float4*)&g[l64 * 4];
    float4 bv = *(const float4*)&bta[l64 * 4];
    float4 o;
    o.x = d.x * rs * gv.x + bv.x;
    o.y = d.y * rs * gv.y + bv.y;
    o.z = d.z * rs * gv.z + bv.z;
    o.w = d.w * rs * gv.w + bv.w;
    *(float4*)&y[base] = o;

    __nv_bfloat16 h0 = __float2bfloat16(o.x), h1 = __float2bfloat16(o.y);
    __nv_bfloat16 h2 = __float2bfloat16(o.z), h3 = __float2bfloat16(o.w);
    __nv_bfloat162 hp0; hp0.x = h0; hp0.y = h1;
    __nv_bfloat162 hp1; hp1.x = h2; hp1.y = h3;
    __nv_bfloat162 lp0, lp1;
    lp0.x = __float2bfloat16(o.x - __bfloat162float(h0));
    lp0.y = __float2bfloat16(o.y - __bfloat162float(h1));
    lp1.x = __float2bfloat16(o.z - __bfloat162float(h2));
    lp1.y = __float2bfloat16(o.w - __bfloat162float(h3));
    uint2 hh, ll;
    hh.x = *(uint32_t*)&hp0; hh.y = *(uint32_t*)&hp1;
    ll.x = *(uint32_t*)&lp0; ll.y = *(uint32_t*)&lp1;
    *(uint2*)&yh[base] = hh;
    *(uint2*)&yl[base] = ll;
}

// ---------------- HMMA GEMM: MTx64 tile, 3-stage pipeline, bf16-split -------
// EPI: 0 = +bias -> fp32 Cf; 1 = gelu(+bias) -> bf16 Ch/Cl; 2 = +bias+Res -> fp32 Cf
template <int MT, int EPI>
__global__ __launch_bounds__(MT == 128 ? 256 : 128) void gemm_mma_kernel(
    const __nv_bfloat16* __restrict__ Ah, const __nv_bfloat16* __restrict__ Al,
    const __nv_bfloat16* __restrict__ Bh, const __nv_bfloat16* __restrict__ Bl,
    const float* __restrict__ bias, const float* Res,
    float* Cf, __nv_bfloat16* Ch, __nv_bfloat16* Cl,
    int N, int K)
{
    extern __shared__ char smem[];
    constexpr int THREADS = (MT == 128) ? 256 : 128;
    constexpr int RS = 40;
    constexpr int A_BYTES = MT * RS * 2;
    constexpr int B_BYTES = 64 * RS * 2;
    constexpr int OFF_AL = A_BYTES;
    constexpr int OFF_BH = 2 * A_BYTES;
    constexpr int SS = 2 * A_BYTES + 2 * B_BYTES;

    uint32_t sb = smem_u32(smem);
    const int tid = threadIdx.x;
    const int m0 = blockIdx.y * MT, n0 = blockIdx.x * 64;

    const int lane = tid & 31, wid = tid >> 5;
    const int wm = (wid >> 1) * 32;
    const int wn = (wid & 1) * 32;
    const int lr = lane & 15, lc = lane >> 4;

    float acc[2][4][4] = {};

    auto load_stage = [&](int buf, int k0) {
        uint32_t st = sb + buf * SS;
#pragma unroll
        for (int u = tid; u < MT * 4; u += THREADS) {
            int r = u >> 2, c = u & 3;
            uint32_t d = st + (uint32_t)(r * RS + c * 8) * 2;
            cp_async16(d,          Ah + (size_t)(m0 + r) * K + k0 + c * 8);
            cp_async16(d + OFF_AL, Al + (size_t)(m0 + r) * K + k0 + c * 8);
        }
#pragma unroll
        for (int u = tid; u < 256; u += THREADS) {
            int r = u >> 2, c = u & 3;
            uint32_t d = st + OFF_BH + (uint32_t)(r * RS + c * 8) * 2;
            cp_async16(d,           Bh + (size_t)(n0 + r) * K + k0 + c * 8);
            cp_async16(d + B_BYTES, Bl + (size_t)(n0 + r) * K + k0 + c * 8);
        }
    };

    const int NST = K >> 5;
    load_stage(0, 0);
    cp_commit();
    if (NST > 1) { load_stage(1, 32); cp_commit(); }

    for (int s = 0; s < NST; s++) {
        if (s + 1 < NST) asm volatile("cp.async.wait_group 1;" ::: "memory");
        else             asm volatile("cp.async.wait_group 0;" ::: "memory");
        __syncthreads();
        if (s + 2 < NST) { load_stage((s + 2) % 3, (s + 2) << 5); cp_commit(); }

        uint32_t st = sb + (s % 3) * SS;
#pragma unroll
        for (int kk = 0; kk < 2; kk++) {
            uint32_t ah[2][4], al[2][4], bh[2][4], bl[2][4];
#pragma unroll
            for (int mt = 0; mt < 2; mt++) {
                uint32_t ad = st + (uint32_t)((wm + mt * 16 + lr) * RS + kk * 16 + lc * 8) * 2;
                ldsm_x4(ah[mt], ad);
                ldsm_x4(al[mt], ad + OFF_AL);
            }
#pragma unroll
            for (int np = 0; np < 2; np++) {
                uint32_t bd = st + OFF_BH + (uint32_t)((wn + np * 16 + lr) * RS + kk * 16 + lc * 8) * 2;
                ldsm_x4(bh[np], bd);
                ldsm_x4(bl[np], bd + B_BYTES);
            }
#pragma unroll
            for (int mt = 0; mt < 2; mt++)
#pragma unroll
                for (int nt = 0; nt < 4; nt++) {
                    uint32_t bhp[2] = { bh[nt >> 1][nt & 1], bh[nt >> 1][2 + (nt & 1)] };
                    uint32_t blp[2] = { bl[nt >> 1][nt & 1], bl[nt >> 1][2 + (nt & 1)] };
                    mma_bf16(acc[mt][nt], ah[mt], bhp);
                    mma_bf16(acc[mt][nt], ah[mt], blp);
                    mma_bf16(acc[mt][nt], al[mt], bhp);
                }
        }
    }

    // ---------------- epilogue -------------------------------------------
    const int tr = lane >> 2;
    const int tc = (lane & 3) * 2;
#pragma unroll
    for (int mt = 0; mt < 2; mt++) {
#pragma unroll
        for (int nt = 0; nt < 4; nt++) {
            int col = n0 + wn + nt * 8 + tc;
            float b0 = bias[col], b1 = bias[col + 1];
#pragma unroll
            for (int half = 0; half < 2; half++) {
                int row = m0 + wm + mt * 16 + tr + half * 8;
                float v0 = acc[mt][nt][half * 2]     + b0;
                float v1 = acc[mt][nt][half * 2 + 1] + b1;
                if (EPI == 1) {
                    v0 = gelu_exact(v0);
                    v1 = gelu_exact(v1);
                    __nv_bfloat16 h0 = __float2bfloat16(v0);
                    __nv_bfloat16 h1 = __float2bfloat16(v1);
                    __nv_bfloat162 hp; hp.x = h0; hp.y = h1;
                    __nv_bfloat162 lp;
                    lp.x = __float2bfloat16(v0 - __bfloat162float(h0));
                    lp.y = __float2bfloat16(v1 - __bfloat162float(h1));
                    *(__nv_bfloat162*)&Ch[(size_t)row * N + col] = hp;
                    *(__nv_bfloat162*)&Cl[(size_t)row * N + col] = lp;
                } else {
                    if (EPI == 2) {
                        float2 rv = *(const float2*)&Res[(size_t)row * N + col];
                        v0 += rv.x; v1 += rv.y;
                    }
                    float2 ov; ov.x = v0; ov.y = v1;
                    *(float2*)&Cf[(size_t)row * N + col] = ov;
                }
            }
        }
    }
}

// ---------------- attention pass A: per-chunk sums (e-split) ----------------
__global__ __launch_bounds__(256) void attn_chunksum_kernel(
    const float* __restrict__ qkv, float* __restrict__ S, float* __restrict__ ks)
{
    __shared__ float Ks[64 * 65];
    __shared__ float Vs[64 * 33];
    int blk = blockIdx.x;
    int eh  = blockIdx.y;          // e-half
    int bh = blk / NCH, c = blk % NCH;
    int b = bh / HH, h = bh % HH;
    int tid = threadIdx.x;

    for (int i = tid; i < 4096; i += 256) {
        int t = i >> 6, d = i & 63;
        int row = b * LL + c * CHUNK + t;
        float kv = qkv[row * 768 + 256 + h * 64 + d];
        Ks[t * 65 + d] = fmaxf(kv, 0.f) + 1e-6f;
    }
    for (int i = tid; i < 2048; i += 256) {
        int t = i >> 5, e = i & 31;
        int row = b * LL + c * CHUNK + t;
        Vs[t * 33 + e] = qkv[row * 768 + 512 + h * 64 + eh * 32 + e];
    }
    __syncthreads();

    int d0 = (tid >> 4) * 4, e0 = (tid & 15) * 2;
    float acc[4][2] = {};
    for (int t = 0; t < 64; t++) {
        float kd[4], ve[2];
#pragma unroll
        for (int i = 0; i < 4; i++) kd[i] = Ks[t * 65 + d0 + i];
#pragma unroll
        for (int j = 0; j < 2; j++) ve[j] = Vs[t * 33 + e0 + j];
#pragma unroll
        for (int i = 0; i < 4; i++)
#pragma unroll
            for (int j = 0; j < 2; j++)
                acc[i][j] += kd[i] * ve[j];
    }
    float* So = S + (bh * NCH + c) * 4096;
#pragma unroll
    for (int i = 0; i < 4; i++)
#pragma unroll
        for (int j = 0; j < 2; j++)
            So[(d0 + i) * 64 + eh * 32 + e0 + j] = acc[i][j];

    if (eh == 0 && tid < 64) {
        float s = 0.f;
        for (int t = 0; t < 64; t++) s += Ks[t * 65 + tid];
        ks[(bh * NCH + c) * 64 + tid] = s;
    }
}

// ---------------- attention pass B: parallel exclusive prefix ---------------
__global__ __launch_bounds__(256) void attn_scan_kernel(
    float* __restrict__ S, float* __restrict__ ks)
{
    int bh = blockIdx.x >> 4;
    int e  = (blockIdx.x & 15) * 256 + threadIdx.x;
    float v[NCH];
#pragma unroll
    for (int c = 0; c < NCH; c++)
        v[c] = S[(size_t)(bh * NCH + c) * 4096 + e];
    float carry = 0.f;
#pragma unroll
    for (int c = 0; c < NCH; c++) {
        S[(size_t)(bh * NCH + c) * 4096 + e] = carry;
        carry += v[c];
    }
    if ((blockIdx.x & 15) == 0 && threadIdx.x < 64) {
        int d = threadIdx.x;
        float kc = 0.f;
#pragma unroll
        for (int c = 0; c < NCH; c++) {
            float t = ks[(bh * NCH + c) * 64 + d];
            ks[(bh * NCH + c) * 64 + d] = kc;
            kc += t;
        }
    }
}

// ---------------- attention pass C: per-chunk output (t-split) --------------
__global__ __launch_bounds__(256) void attn_out_kernel(
    const float* __restrict__ qkv, const float* __restrict__ S,
    const float* __restrict__ ks,
    __nv_bfloat16* __restrict__ oh, __nv_bfloat16* __restrict__ ol)
{
    extern __shared__ float sm[];
    float* Qs   = sm;              // 32x65
    float* Ps   = sm + 2080;       // 64x65
    float* As   = sm + 6240;       // 32x65
    float* KV   = sm + 8320;       // 64x65
    float* dens = sm + 12480;      // 32
    float* kps  = sm + 12512;      // 64

    int blk = blockIdx.x;
    int th  = blockIdx.y;          // t-half
    int bh = blk / NCH, c = blk % NCH;
    int b = bh / HH, h = bh % HH;
    int tid = threadIdx.x;
    const float* Sc = S  + (size_t)(bh * NCH + c) * 4096;
    const float* kc = ks + (bh * NCH + c) * 64;
    const int t0 = th * 32;

    // load Q half (phi) and P full
    for (int i = tid; i < 2048; i += 256) {
        int t = i >> 6, d = i & 63;
        int row = b * LL + c * CHUNK + t0 + t;
        float qv = qkv[row * 768 + h * 64 + d];
        Qs[t * 65 + d] = fmaxf(qv, 0.f) + 1e-6f;
    }
    for (int i = tid; i < 4096; i += 256) {
        int t = i >> 6, e = i & 63;
        Ps[t * 65 + e] = Sc[i];
    }
    if (tid < 64) kps[tid] = kc[tid];
    __syncthreads();

    int i0 = (tid >> 4) * 2, j0 = (tid & 15) * 4;
    float acc[2][4] = {};

    // acc = Q @ P
    for (int d = 0; d < 64; d++) {
        float q[2], p[4];
#pragma unroll
        for (int i = 0; i < 2; i++) q[i] = Qs[(i0 + i) * 65 + d];
#pragma unroll
        for (int j = 0; j < 4; j++) p[j] = Ps[d * 65 + j0 + j];
#pragma unroll
        for (int i = 0; i < 2; i++)
#pragma unroll
            for (int j = 0; j < 4; j++)
                acc[i][j] += q[i] * p[j];
    }
    if (tid < 32) {
        float s = 0.f;
        for (int d = 0; d < 64; d++) s += Qs[tid * 65 + d] * kps[d];
        dens[tid] = s;
    }

    // load K (phi) full
    for (int i = tid; i < 4096; i += 256) {
        int t = i >> 6, d = i & 63;
        int row = b * LL + c * CHUNK + t;
        float kv = qkv[row * 768 + 256 + h * 64 + d];
        KV[t * 65 + d] = fmaxf(kv, 0.f) + 1e-6f;
    }
    __syncthreads();

    // A = tril(Q K^T) for rows t0..t0+31
    {
        float av[2][4] = {};
        for (int d = 0; d < 64; d++) {
            float q[2], kk[4];
#pragma unroll
            for (int i = 0; i < 2; i++) q[i]  = Qs[(i0 + i) * 65 + d];
#pragma unroll
            for (int j = 0; j < 4; j++) kk[j] = KV[(j0 + j) * 65 + d];
#pragma unroll
            for (int i = 0; i < 2; i++)
#pragma unroll
                for (int j = 0; j < 4; j++)
                    av[i][j] += q[i] * kk[j];
        }
#pragma unroll
        for (int i = 0; i < 2; i++)
#pragma unroll
            for (int j = 0; j < 4; j++)
                As[(i0 + i) * 65 + (j0 + j)] =
                    ((j0 + j) <= (t0 + i0 + i)) ? av[i][j] : 0.f;
    }
    __syncthreads();

    // den += rowsum(A); load V
    if (tid < 32) {
        float rs = 0.f;
        for (int j = 0; j < 64; j++) rs += As[tid * 65 + j];
        dens[tid] += rs;
    }
    for (int i = tid; i < 4096; i += 256) {
        int t = i >> 6, d = i & 63;
        int row = b * LL + c * CHUNK + t;
        KV[t * 65 + d] = qkv[row * 768 + 512 + h * 64 + d];
    }
    __syncthreads();

    // acc += A @ V; write bf16 hi/lo
    for (int j = 0; j < 64; j++) {
        float av[2], vv[4];
#pragma unroll
        for (int i = 0; i < 2; i++) av[i] = As[(i0 + i) * 65 + j];
#pragma unroll
        for (int jj = 0; jj < 4; jj++) vv[jj] = KV[j * 65 + j0 + jj];
#pragma unroll
        for (int i = 0; i < 2; i++)
#pragma unroll
            for (int jj = 0; jj < 4; jj++)
                acc[i][jj] += av[i] * vv[jj];
    }
#pragma unroll
    for (int i = 0; i < 2; i++) {
        float dn = fmaxf(dens[i0 + i], 1e-6f);
        int row = b * LL + c * CHUNK + t0 + i0 + i;
        float inv = 1.0f / dn;
#pragma unroll
        for (int j = 0; j < 4; j++) {
            float v = acc[i][j] * inv;
            __nv_bfloat16 hh = __float2bfloat16(v);
            size_t idx = (size_t)row * EE + h * 64 + j0 + j;
            oh[idx] = hh;
            ol[idx] = __float2bfloat16(v - __bfloat162float(hh));
        }
    }
}

// ---------------- pred: state tokens @ pred_w + pred_b ---------------------
__global__ __launch_bounds__(256) void pred_kernel(
    const float* __restrict__ xn, const float* __restrict__ pred_w,
    const float* __restrict__ pred_b, float* __restrict__ out)
{
    int bk = blockIdx.x;
    int b = bk / KSTEP, k = bk % KSTEP;
    int row = b * LL + 3 * k + 1;
    __shared__ float xr[EE];
    int tid = threadIdx.x;
    xr[tid] = xn[row * EE + tid];
    __syncthreads();
    int w = tid >> 5, lane = tid & 31;
    if (w < NACT) {
        float s = 0.f;
        for (int e = lane; e < EE; e += 32) s += xr[e] * pred_w[e * NACT + w];
#pragma unroll
        for (int o = 16; o; o >>= 1) s += __shfl_xor_sync(0xffffffffu, s, o);
        if (lane == 0) out[bk * NACT + w] = s + pred_b[w];
    }
}

// ---------------- launch ----------------------------------------------------
extern "C" void kernel_launch(void* const* d_in, const int* in_sizes, int n_in,
                              void* d_out, int out_size)
{
    const float* rtg      = (const float*)d_in[0];
    const float* state    = (const float*)d_in[1];
    const float* action   = (const float*)d_in[2];
    const float* rtg_w    = (const float*)d_in[3];
    const float* rtg_b    = (const float*)d_in[4];
    const float* state_w  = (const float*)d_in[5];
    const float* state_b  = (const float*)d_in[6];
    const float* action_w = (const float*)d_in[7];
    const float* action_b = (const float*)d_in[8];
    const float* pos_emb  = (const float*)d_in[9];
    const float* norm1_g  = (const float*)d_in[10];
    const float* norm1_b  = (const float*)d_in[11];
    const float* qkv_w    = (const float*)d_in[12];
    const float* qkv_b    = (const float*)d_in[13];
    const float* out_w    = (const float*)d_in[14];
    const float* out_b    = (const float*)d_in[15];
    const float* norm2_g  = (const float*)d_in[16];
    const float* norm2_b  = (const float*)d_in[17];
    const float* ffn1_w   = (const float*)d_in[18];
    const float* ffn1_b   = (const float*)d_in[19];
    const float* ffn2_w   = (const float*)d_in[20];
    const float* ffn2_b   = (const float*)d_in[21];
    const float* normf_g  = (const float*)d_in[22];
    const float* normf_b  = (const float*)d_in[23];
    const float* pred_w   = (const float*)d_in[24];
    const float* pred_b   = (const float*)d_in[25];

    float *x, *xn, *qkv, *S, *ks;
    __nv_bfloat16 *xh, *xl, *oh, *ol, *ffh, *ffl, *wh, *wl;
    cudaGetSymbolAddress((void**)&x,   g_x);
    cudaGetSymbolAddress((void**)&xn,  g_xn);
    cudaGetSymbolAddress((void**)&qkv, g_qkv);
    cudaGetSymbolAddress((void**)&S,   g_S);
    cudaGetSymbolAddress((void**)&ks,  g_ks);
    cudaGetSymbolAddress((void**)&xh,  g_xh);
    cudaGetSymbolAddress((void**)&xl,  g_xl);
    cudaGetSymbolAddress((void**)&oh,  g_oh);
    cudaGetSymbolAddress((void**)&ol,  g_ol);
    cudaGetSymbolAddress((void**)&ffh, g_ffh);
    cudaGetSymbolAddress((void**)&ffl, g_ffl);
    cudaGetSymbolAddress((void**)&wh,  g_wh);
    cudaGetSymbolAddress((void**)&wl,  g_wl);

    const int SMEM_C    = 12576 * 4;        // attn_out
    const int SMEM_G128 = 3 * 30720;        // 92160
    const int SMEM_G64  = 3 * 20480;        // 61440
    cudaFuncSetAttribute(attn_out_kernel,
                         cudaFuncAttributeMaxDynamicSharedMemorySize, SMEM_C);
    cudaFuncSetAttribute((const void*)gemm_mma_kernel<128, 0>,
                         cudaFuncAttributeMaxDynamicSharedMemorySize, SMEM_G128);
    cudaFuncSetAttribute((const void*)gemm_mma_kernel<128, 1>,
                         cudaFuncAttributeMaxDynamicSharedMemorySize, SMEM_G128);
    cudaFuncSetAttribute((const void*)gemm_mma_kernel<64, 2>,
                         cudaFuncAttributeMaxDynamicSharedMemorySize, SMEM_G64);

    wsplit_kernel<<<dim3(32, 32, 8), dim3(32, 8)>>>(qkv_w, out_w, ffn1_w, ffn2_w, wh, wl);

    // embed + layer-0 LN1 fused
    embed_ln_kernel<<<MTOK, 256>>>(rtg, state, action, rtg_w, rtg_b, state_w, state_b,
                                   action_w, action_b, pos_emb,
                                   norm1_g, norm1_b, x, xh, xl);

    for (int layer = 0; layer < NLAYER; layer++) {
        const float* n2g = norm2_g + layer * EE;
        const float* n2b = norm2_b + layer * EE;
        const float* qb  = qkv_b  + layer * 3 * EE;
        const float* ob  = out_b  + layer * EE;
        const float* f1b = ffn1_b + layer * FFD;
        const float* f2b = ffn2_b + layer * EE;
        size_t qoff  = (size_t)layer * 196608;
        size_t ooff  = 393216  + (size_t)layer * 65536;
        size_t f1off = 524288  + (size_t)layer * 262144;
        size_t f2off = 1048576 + (size_t)layer * 262144;

        if (layer > 0) {
            ln4_kernel<<<MTOK / 4, 256>>>(x, norm1_g + layer * EE, norm1_b + layer * EE,
                                          xn, xh, xl);
        }

        // qkv: [3072,256] @ [256,768]
        gemm_mma_kernel<128, 0><<<dim3(12, 24), 256, SMEM_G128>>>(
            xh, xl, wh + qoff, wl + qoff, qb, nullptr, qkv, nullptr, nullptr, 768, 256);

        attn_chunksum_kernel<<<dim3(NBH * NCH, 2), 256>>>(qkv, S, ks);
        attn_scan_kernel<<<NBH * 16, 256>>>(S, ks);
        attn_out_kernel<<<dim3(NBH * NCH, 2), 256, SMEM_C>>>(qkv, S, ks, oh, ol);

        // out proj: [3072,256] @ [256,256] + bias + residual
        gemm_mma_kernel<64, 2><<<dim3(4, 48), 128, SMEM_G64>>>(
            oh, ol, wh + ooff, wl + ooff, ob, x, x, nullptr, nullptr, 256, 256);

        ln4_kernel<<<MTOK / 4, 256>>>(x, n2g, n2b, xn, xh, xl);

        // ffn1: [3072,256] @ [256,1024] + bias + GELU -> bf16 hi/lo
        gemm_mma_kernel<128, 1><<<dim3(16, 24), 256, SMEM_G128>>>(
            xh, xl, wh + f1off, wl + f1off, f1b, nullptr, nullptr, ffh, ffl, 1024, 256);

        // ffn2: [3072,1024] @ [1024,256] + bias + residual
        gemm_mma_kernel<64, 2><<<dim3(4, 48), 128, SMEM_G64>>>(
            ffh, ffl, wh + f2off, wl + f2off, f2b, x, x, nullptr, nullptr, 256, 1024);
    }

    ln4_kernel<<<MTOK / 4, 256>>>(x, normf_g, normf_b, xn, xh, xl);
    pred_kernel<<<BB * KSTEP, 256>>>(xn, pred_w, pred_b, (float*)d_out);
}

// round 6
// speedup vs baseline: 2.6575x; 1.1194x over previous
#include <cuda_runtime.h>
#include <cuda_bf16.h>
#include <math.h>
#include <stdint.h>

#define BB     2
#define KSTEP  512
#define SDIM   60
#define NACT   5
#define EE     256
#define HH     4
#define DD     64
#define FFD    1024
#define NLAYER 2
#define LL     1536          // 3*KSTEP
#define MTOK   3072          // BB*LL
#define CHUNK  64
#define NCH    24            // LL/CHUNK
#define NBH    8             // BB*HH

#define WTOT   1572864       // total split-weight elements (bf16)
#define PS     68            // padded smem row stride (floats), 16B aligned

// ---------------- scratch (device globals; no allocation) ----------------
__device__ float g_x  [MTOK * EE];
__device__ float g_xn [MTOK * EE];
__device__ float g_qkv[MTOK * 3 * EE];
__device__ float g_S  [NBH * NCH * DD * DD];
__device__ float g_ks [NBH * NCH * DD];
__device__ __nv_bfloat16 g_xh [MTOK * EE];
__device__ __nv_bfloat16 g_xl [MTOK * EE];
__device__ __nv_bfloat16 g_oh [MTOK * EE];
__device__ __nv_bfloat16 g_ol [MTOK * EE];
__device__ __nv_bfloat16 g_ffh[MTOK * FFD];
__device__ __nv_bfloat16 g_ffl[MTOK * FFD];
__device__ __nv_bfloat16 g_wh [WTOT];
__device__ __nv_bfloat16 g_wl [WTOT];

// ---------------- helpers ----------------------------------------------------
__device__ __forceinline__ uint32_t smem_u32(const void* p) {
    uint32_t a;
    asm("{ .reg .u64 t; cvta.to.shared.u64 t, %1; cvt.u32.u64 %0, t; }" : "=r"(a) : "l"(p));
    return a;
}
__device__ __forceinline__ void cp_async16(uint32_t dst, const void* src) {
    asm volatile("cp.async.cg.shared.global [%0], [%1], 16;" :: "r"(dst), "l"(src) : "memory");
}
__device__ __forceinline__ void cp_commit() { asm volatile("cp.async.commit_group;" ::: "memory"); }

__device__ __forceinline__ void ldsm_x4(uint32_t* r, uint32_t addr) {
    asm volatile("ldmatrix.sync.aligned.m8n8.x4.shared.b16 {%0,%1,%2,%3}, [%4];"
                 : "=r"(r[0]), "=r"(r[1]), "=r"(r[2]), "=r"(r[3]) : "r"(addr));
}
__device__ __forceinline__ void mma_bf16(float* c, const uint32_t* a, const uint32_t* b) {
    asm volatile(
        "mma.sync.aligned.m16n8k16.row.col.f32.bf16.bf16.f32 "
        "{%0,%1,%2,%3}, {%4,%5,%6,%7}, {%8,%9}, {%0,%1,%2,%3};"
        : "+f"(c[0]), "+f"(c[1]), "+f"(c[2]), "+f"(c[3])
        : "r"(a[0]), "r"(a[1]), "r"(a[2]), "r"(a[3]), "r"(b[0]), "r"(b[1]));
}

__device__ __forceinline__ float gelu_exact(float x) {
    return 0.5f * x * (1.0f + erff(x * 0.70710678118654752f));
}

// ---------------- weight transpose + bf16 split -----------------------------
__global__ __launch_bounds__(256) void wsplit_kernel(
    const float* __restrict__ qkv_w, const float* __restrict__ out_w,
    const float* __restrict__ f1w, const float* __restrict__ f2w,
    __nv_bfloat16* __restrict__ Wh, __nv_bfloat16* __restrict__ Wl)
{
    const float* src; int Kd, Nd; size_t doff;
    switch (blockIdx.z) {
        case 0: src = qkv_w;          Kd = 256;  Nd = 768;  doff = 0;       break;
        case 1: src = qkv_w + 196608; Kd = 256;  Nd = 768;  doff = 196608;  break;
        case 2: src = out_w;          Kd = 256;  Nd = 256;  doff = 393216;  break;
        case 3: src = out_w + 65536;  Kd = 256;  Nd = 256;  doff = 458752;  break;
        case 4: src = f1w;            Kd = 256;  Nd = 1024; doff = 524288;  break;
        case 5: src = f1w + 262144;   Kd = 256;  Nd = 1024; doff = 786432;  break;
        case 6: src = f2w;            Kd = 1024; Nd = 256;  doff = 1048576; break;
        default:src = f2w + 262144;   Kd = 1024; Nd = 256;  doff = 1310720; break;
    }
    int nt = blockIdx.x * 32, kt = blockIdx.y * 32;
    if (nt >= Nd || kt >= Kd) return;
    __shared__ float t[32][33];
#pragma unroll
    for (int i = 0; i < 4; i++) {
        int r = kt + threadIdx.y + i * 8;
        t[threadIdx.y + i * 8][threadIdx.x] = src[(size_t)r * Nd + nt + threadIdx.x];
    }
    __syncthreads();
#pragma unroll
    for (int i = 0; i < 4; i++) {
        int n = nt + threadIdx.y + i * 8;
        int k = kt + threadIdx.x;
        float v = t[threadIdx.x][threadIdx.y + i * 8];
        __nv_bfloat16 h = __float2bfloat16(v);
        Wh[doff + (size_t)n * Kd + k] = h;
        Wl[doff + (size_t)n * Kd + k] = __float2bfloat16(v - __bfloat162float(h));
    }
}

// ---------------- embed fused with layer-0 LN1 ------------------------------
__global__ __launch_bounds__(256) void embed_ln_kernel(
    const float* __restrict__ rtg, const float* __restrict__ state,
    const float* __restrict__ action,
    const float* __restrict__ rtg_w, const float* __restrict__ rtg_b,
    const float* __restrict__ state_w, const float* __restrict__ state_b,
    const float* __restrict__ action_w, const float* __restrict__ action_b,
    const float* __restrict__ pos,
    const float* __restrict__ g, const float* __restrict__ bta,
    float* __restrict__ x,
    __nv_bfloat16* __restrict__ yh, __nv_bfloat16* __restrict__ yl)
{
    int tok = blockIdx.x;
    int e   = threadIdx.x;
    int b   = tok / LL;
    int l   = tok % LL;
    int k   = l / 3;
    int typ = l % 3;
    float acc = pos[k * EE + e];
    if (typ == 0) {
        acc += rtg[b * KSTEP + k] * rtg_w[e] + rtg_b[e];
    } else if (typ == 1) {
        const float* s = state + (b * KSTEP + k) * SDIM;
        float sum = 0.f;
        for (int i = 0; i < SDIM; i++) sum += s[i] * state_w[i * EE + e];
        acc += sum + state_b[e];
    } else {
        const float* a = action + (b * KSTEP + k) * NACT;
        float sum = 0.f;
#pragma unroll
        for (int i = 0; i < NACT; i++) sum += a[i] * action_w[i * EE + e];
        acc += sum + action_b[e];
    }
    x[tok * EE + e] = acc;

    __shared__ float red[8];
    float s = acc;
#pragma unroll
    for (int o = 16; o; o >>= 1) s += __shfl_xor_sync(0xffffffffu, s, o);
    if ((e & 31) == 0) red[e >> 5] = s;
    __syncthreads();
    if (e < 8) {
        float t = red[e];
#pragma unroll
        for (int o = 4; o; o >>= 1) t += __shfl_xor_sync(0xffu, t, o);
        if (e == 0) red[0] = t;
    }
    __syncthreads();
    float mean = red[0] * (1.0f / EE);
    __syncthreads();
    float d  = acc - mean;
    float s2 = d * d;
#pragma unroll
    for (int o = 16; o; o >>= 1) s2 += __shfl_xor_sync(0xffffffffu, s2, o);
    if ((e & 31) == 0) red[e >> 5] = s2;
    __syncthreads();
    if (e < 8) {
        float t = red[e];
#pragma unroll
        for (int o = 4; o; o >>= 1) t += __shfl_xor_sync(0xffu, t, o);
        if (e == 0) red[0] = t;
    }
    __syncthreads();
    float var = red[0] * (1.0f / EE);
    float r = rsqrtf(var + 1e-5f);
    float yv = d * r * g[e] + bta[e];
    __nv_bfloat16 h = __float2bfloat16(yv);
    yh[tok * EE + e] = h;
    yl[tok * EE + e] = __float2bfloat16(yv - __bfloat162float(h));
}

// ---------------- LayerNorm: 4 rows/block, float4 ---------------------------
__global__ __launch_bounds__(256) void ln4_kernel(
    const float* __restrict__ x, const float* __restrict__ g,
    const float* __restrict__ bta, float* __restrict__ y,
    __nv_bfloat16* __restrict__ yh, __nv_bfloat16* __restrict__ yl)
{
    __shared__ float red[16];
    int tid = threadIdx.x;
    int r   = tid >> 6;
    int l64 = tid & 63;
    int w   = tid >> 5;
    int lane = tid & 31;
    int row = blockIdx.x * 4 + r;
    size_t base = (size_t)row * EE + l64 * 4;

    float4 v = *(const float4*)&x[base];
    float s = v.x + v.y + v.z + v.w;
#pragma unroll
    for (int o = 16; o; o >>= 1) s += __shfl_xor_sync(0xffffffffu, s, o);
    if (lane == 0) red[w] = s;
    __syncthreads();
    float mean = (red[2 * r] + red[2 * r + 1]) * (1.0f / EE);

    float4 d;
    d.x = v.x - mean; d.y = v.y - mean; d.z = v.z - mean; d.w = v.w - mean;
    float s2 = d.x * d.x + d.y * d.y + d.z * d.z + d.w * d.w;
#pragma unroll
    for (int o = 16; o; o >>= 1) s2 += __shfl_xor_sync(0xffffffffu, s2, o);
    if (lane == 0) red[8 + w] = s2;
    __syncthreads();
    float var = (red[8 + 2 * r] + red[8 + 2 * r + 1]) * (1.0f / EE);
    float rs = rsqrtf(var + 1e-5f);

    float4 gv = *(const float4*)&g[l64 * 4];
    float4 bv = *(const float4*)&bta[l64 * 4];
    float4 o;
    o.x = d.x * rs * gv.x + bv.x;
    o.y = d.y * rs * gv.y + bv.y;
    o.z = d.z * rs * gv.z + bv.z;
    o.w = d.w * rs * gv.w + bv.w;
    *(float4*)&y[base] = o;

    __nv_bfloat16 h0 = __float2bfloat16(o.x), h1 = __float2bfloat16(o.y);
    __nv_bfloat16 h2 = __float2bfloat16(o.z), h3 = __float2bfloat16(o.w);
    __nv_bfloat162 hp0; hp0.x = h0; hp0.y = h1;
    __nv_bfloat162 hp1; hp1.x = h2; hp1.y = h3;
    __nv_bfloat162 lp0, lp1;
    lp0.x = __float2bfloat16(o.x - __bfloat162float(h0));
    lp0.y = __float2bfloat16(o.y - __bfloat162float(h1));
    lp1.x = __float2bfloat16(o.z - __bfloat162float(h2));
    lp1.y = __float2bfloat16(o.w - __bfloat162float(h3));
    uint2 hh, ll;
    hh.x = *(uint32_t*)&hp0; hh.y = *(uint32_t*)&hp1;
    ll.x = *(uint32_t*)&lp0; ll.y = *(uint32_t*)&lp1;
    *(uint2*)&yh[base] = hh;
    *(uint2*)&yl[base] = ll;
}

// ---------------- HMMA GEMM: MTx64 tile, 3-stage pipeline, bf16-split -------
template <int MT, int EPI>
__global__ __launch_bounds__(MT == 128 ? 256 : 128) void gemm_mma_kernel(
    const __nv_bfloat16* __restrict__ Ah, const __nv_bfloat16* __restrict__ Al,
    const __nv_bfloat16* __restrict__ Bh, const __nv_bfloat16* __restrict__ Bl,
    const float* __restrict__ bias, const float* Res,
    float* Cf, __nv_bfloat16* Ch, __nv_bfloat16* Cl,
    int N, int K)
{
    extern __shared__ char smem[];
    constexpr int THREADS = (MT == 128) ? 256 : 128;
    constexpr int RS = 40;
    constexpr int A_BYTES = MT * RS * 2;
    constexpr int B_BYTES = 64 * RS * 2;
    constexpr int OFF_AL = A_BYTES;
    constexpr int OFF_BH = 2 * A_BYTES;
    constexpr int SS = 2 * A_BYTES + 2 * B_BYTES;

    uint32_t sb = smem_u32(smem);
    const int tid = threadIdx.x;
    const int m0 = blockIdx.y * MT, n0 = blockIdx.x * 64;

    const int lane = tid & 31, wid = tid >> 5;
    const int wm = (wid >> 1) * 32;
    const int wn = (wid & 1) * 32;
    const int lr = lane & 15, lc = lane >> 4;

    float acc[2][4][4] = {};

    auto load_stage = [&](int buf, int k0) {
        uint32_t st = sb + buf * SS;
#pragma unroll
        for (int u = tid; u < MT * 4; u += THREADS) {
            int r = u >> 2, c = u & 3;
            uint32_t d = st + (uint32_t)(r * RS + c * 8) * 2;
            cp_async16(d,          Ah + (size_t)(m0 + r) * K + k0 + c * 8);
            cp_async16(d + OFF_AL, Al + (size_t)(m0 + r) * K + k0 + c * 8);
        }
#pragma unroll
        for (int u = tid; u < 256; u += THREADS) {
            int r = u >> 2, c = u & 3;
            uint32_t d = st + OFF_BH + (uint32_t)(r * RS + c * 8) * 2;
            cp_async16(d,           Bh + (size_t)(n0 + r) * K + k0 + c * 8);
            cp_async16(d + B_BYTES, Bl + (size_t)(n0 + r) * K + k0 + c * 8);
        }
    };

    const int NST = K >> 5;
    load_stage(0, 0);
    cp_commit();
    if (NST > 1) { load_stage(1, 32); cp_commit(); }

    for (int s = 0; s < NST; s++) {
        if (s + 1 < NST) asm volatile("cp.async.wait_group 1;" ::: "memory");
        else             asm volatile("cp.async.wait_group 0;" ::: "memory");
        __syncthreads();
        if (s + 2 < NST) { load_stage((s + 2) % 3, (s + 2) << 5); cp_commit(); }

        uint32_t st = sb + (s % 3) * SS;
#pragma unroll
        for (int kk = 0; kk < 2; kk++) {
            uint32_t ah[2][4], al[2][4], bh[2][4], bl[2][4];
#pragma unroll
            for (int mt = 0; mt < 2; mt++) {
                uint32_t ad = st + (uint32_t)((wm + mt * 16 + lr) * RS + kk * 16 + lc * 8) * 2;
                ldsm_x4(ah[mt], ad);
                ldsm_x4(al[mt], ad + OFF_AL);
            }
#pragma unroll
            for (int np = 0; np < 2; np++) {
                uint32_t bd = st + OFF_BH + (uint32_t)((wn + np * 16 + lr) * RS + kk * 16 + lc * 8) * 2;
                ldsm_x4(bh[np], bd);
                ldsm_x4(bl[np], bd + B_BYTES);
            }
#pragma unroll
            for (int mt = 0; mt < 2; mt++)
#pragma unroll
                for (int nt = 0; nt < 4; nt++) {
                    uint32_t bhp[2] = { bh[nt >> 1][nt & 1], bh[nt >> 1][2 + (nt & 1)] };
                    uint32_t blp[2] = { bl[nt >> 1][nt & 1], bl[nt >> 1][2 + (nt & 1)] };
                    mma_bf16(acc[mt][nt], ah[mt], bhp);
                    mma_bf16(acc[mt][nt], ah[mt], blp);
                    mma_bf16(acc[mt][nt], al[mt], bhp);
                }
        }
    }

    const int tr = lane >> 2;
    const int tc = (lane & 3) * 2;
#pragma unroll
    for (int mt = 0; mt < 2; mt++) {
#pragma unroll
        for (int nt = 0; nt < 4; nt++) {
            int col = n0 + wn + nt * 8 + tc;
            float b0 = bias[col], b1 = bias[col + 1];
#pragma unroll
            for (int half = 0; half < 2; half++) {
                int row = m0 + wm + mt * 16 + tr + half * 8;
                float v0 = acc[mt][nt][half * 2]     + b0;
                float v1 = acc[mt][nt][half * 2 + 1] + b1;
                if (EPI == 1) {
                    v0 = gelu_exact(v0);
                    v1 = gelu_exact(v1);
                    __nv_bfloat16 h0 = __float2bfloat16(v0);
                    __nv_bfloat16 h1 = __float2bfloat16(v1);
                    __nv_bfloat162 hp; hp.x = h0; hp.y = h1;
                    __nv_bfloat162 lp;
                    lp.x = __float2bfloat16(v0 - __bfloat162float(h0));
                    lp.y = __float2bfloat16(v1 - __bfloat162float(h1));
                    *(__nv_bfloat162*)&Ch[(size_t)row * N + col] = hp;
                    *(__nv_bfloat162*)&Cl[(size_t)row * N + col] = lp;
                } else {
                    if (EPI == 2) {
                        float2 rv = *(const float2*)&Res[(size_t)row * N + col];
                        v0 += rv.x; v1 += rv.y;
                    }
                    float2 ov; ov.x = v0; ov.y = v1;
                    *(float2*)&Cf[(size_t)row * N + col] = ov;
                }
            }
        }
    }
}

// ---------------- attention pass A: per-chunk sums (vectorized) -------------
__global__ __launch_bounds__(256) void attn_chunksum_kernel(
    const float* __restrict__ qkv, float* __restrict__ S, float* __restrict__ ks)
{
    __shared__ float Ks[64 * PS];
    __shared__ float Vs[64 * PS];
    int blk = blockIdx.x;
    int bh = blk / NCH, c = blk % NCH;
    int b = bh / HH, h = bh % HH;
    int tid = threadIdx.x;

#pragma unroll
    for (int i = tid; i < 4096; i += 256) {
        int t = i >> 6, d = i & 63;
        int row = b * LL + c * CHUNK + t;
        float kv = qkv[row * 768 + 256 + h * 64 + d];
        Ks[t * PS + d] = fmaxf(kv, 0.f) + 1e-6f;
        Vs[t * PS + d] = qkv[row * 768 + 512 + h * 64 + d];
    }
    __syncthreads();

    int d0 = (tid >> 4) * 4, e0 = (tid & 15) * 4;
    float acc[4][4] = {};
#pragma unroll 4
    for (int t = 0; t < 64; t++) {
        float kd[4], ve[4];
        *(float4*)kd = *(const float4*)&Ks[t * PS + d0];
        *(float4*)ve = *(const float4*)&Vs[t * PS + e0];
#pragma unroll
        for (int i = 0; i < 4; i++)
#pragma unroll
            for (int j = 0; j < 4; j++)
                acc[i][j] += kd[i] * ve[j];
    }
    float* So = S + (size_t)(bh * NCH + c) * 4096;
#pragma unroll
    for (int i = 0; i < 4; i++) {
        float4 o1 = make_float4(acc[i][0], acc[i][1], acc[i][2], acc[i][3]);
        *(float4*)&So[(d0 + i) * 64 + e0] = o1;
    }

    if (tid < 64) {
        float s = 0.f;
#pragma unroll 8
        for (int t = 0; t < 64; t++) s += Ks[t * PS + tid];
        ks[(bh * NCH + c) * 64 + tid] = s;
    }
}

// ---------------- attention pass B: parallel exclusive prefix ---------------
__global__ __launch_bounds__(256) void attn_scan_kernel(
    float* __restrict__ S, float* __restrict__ ks)
{
    int bh = blockIdx.x >> 4;
    int e  = (blockIdx.x & 15) * 256 + threadIdx.x;
    float v[NCH];
#pragma unroll
    for (int c = 0; c < NCH; c++)
        v[c] = S[(size_t)(bh * NCH + c) * 4096 + e];
    float carry = 0.f;
#pragma unroll
    for (int c = 0; c < NCH; c++) {
        S[(size_t)(bh * NCH + c) * 4096 + e] = carry;
        carry += v[c];
    }
    if ((blockIdx.x & 15) == 0 && threadIdx.x < 64) {
        int d = threadIdx.x;
        float kc = 0.f;
#pragma unroll
        for (int c = 0; c < NCH; c++) {
            float t = ks[(bh * NCH + c) * 64 + d];
            ks[(bh * NCH + c) * 64 + d] = kc;
            kc += t;
        }
    }
}

// ---------------- attention pass C: full-chunk output (vectorized) ----------
__global__ __launch_bounds__(256) void attn_out_kernel(
    const float* __restrict__ qkv, const float* __restrict__ S,
    const float* __restrict__ ks,
    __nv_bfloat16* __restrict__ oh, __nv_bfloat16* __restrict__ ol)
{
    extern __shared__ float sm[];
    float* Qs   = sm;               // 64 x PS (phi(q))
    float* Ts   = sm + 64 * PS;     // 64 x PS : P, then K, then V
    float* As   = sm + 128 * PS;    // 64 x PS : masked QK^T
    float* dens = sm + 192 * PS;    // 64
    float* kps  = dens + 64;        // 64

    int blk = blockIdx.x;
    int bh = blk / NCH, c = blk % NCH;
    int b = bh / HH, h = bh % HH;
    int tid = threadIdx.x;
    const float* Sc = S  + (size_t)(bh * NCH + c) * 4096;
    const float* kc = ks + (bh * NCH + c) * 64;

    // load Q (phi) and P (exclusive kv prefix)
#pragma unroll
    for (int i = tid; i < 4096; i += 256) {
        int t = i >> 6, d = i & 63;
        int row = b * LL + c * CHUNK + t;
        float qv = qkv[row * 768 + h * 64 + d];
        Qs[t * PS + d] = fmaxf(qv, 0.f) + 1e-6f;
        Ts[t * PS + d] = Sc[i];
    }
    if (tid < 64) kps[tid] = kc[tid];
    __syncthreads();

    const int i0 = (tid >> 4) * 4, j0 = (tid & 15) * 4;
    float acc[4][4] = {};

    // acc = Q @ P   (d-unrolled by 4, float4 loads)
#pragma unroll 2
    for (int d = 0; d < 64; d += 4) {
        float qv[4][4], pv[4][4];
#pragma unroll
        for (int i = 0; i < 4; i++)
            *(float4*)qv[i] = *(const float4*)&Qs[(i0 + i) * PS + d];
#pragma unroll
        for (int dd = 0; dd < 4; dd++)
            *(float4*)pv[dd] = *(const float4*)&Ts[(d + dd) * PS + j0];
#pragma unroll
        for (int i = 0; i < 4; i++)
#pragma unroll
            for (int j = 0; j < 4; j++)
#pragma unroll
                for (int dd = 0; dd < 4; dd++)
                    acc[i][j] += qv[i][dd] * pv[dd][j];
    }
    if (tid < 64) {
        float s = 0.f;
#pragma unroll
        for (int d = 0; d < 64; d += 4) {
            float4 q4 = *(const float4*)&Qs[tid * PS + d];
            float4 k4 = *(const float4*)&kps[d];
            s += q4.x * k4.x + q4.y * k4.y + q4.z * k4.z + q4.w * k4.w;
        }
        dens[tid] = s;
    }
    __syncthreads();

    // load K (phi) into Ts
#pragma unroll
    for (int i = tid; i < 4096; i += 256) {
        int t = i >> 6, d = i & 63;
        int row = b * LL + c * CHUNK + t;
        float kv = qkv[row * 768 + 256 + h * 64 + d];
        Ts[t * PS + d] = fmaxf(kv, 0.f) + 1e-6f;
    }
    __syncthreads();

    // A = tril(Q K^T)
    {
        float av[4][4] = {};
#pragma unroll 2
        for (int d = 0; d < 64; d += 4) {
            float qv[4][4], kv[4][4];
#pragma unroll
            for (int i = 0; i < 4; i++)
                *(float4*)qv[i] = *(const float4*)&Qs[(i0 + i) * PS + d];
#pragma unroll
            for (int j = 0; j < 4; j++)
                *(float4*)kv[j] = *(const float4*)&Ts[(j0 + j) * PS + d];
#pragma unroll
            for (int i = 0; i < 4; i++)
#pragma unroll
                for (int j = 0; j < 4; j++)
#pragma unroll
                    for (int dd = 0; dd < 4; dd++)
                        av[i][j] += qv[i][dd] * kv[j][dd];
        }
#pragma unroll
        for (int i = 0; i < 4; i++) {
            float4 o;
            o.x = (j0 + 0 <= i0 + i) ? av[i][0] : 0.f;
            o.y = (j0 + 1 <= i0 + i) ? av[i][1] : 0.f;
            o.z = (j0 + 2 <= i0 + i) ? av[i][2] : 0.f;
            o.w = (j0 + 3 <= i0 + i) ? av[i][3] : 0.f;
            *(float4*)&As[(i0 + i) * PS + j0] = o;
        }
    }
    __syncthreads();

    // den += rowsum(A); load V into Ts
    if (tid < 64) {
        float rs = 0.f;
#pragma unroll
        for (int j = 0; j < 64; j += 4) {
            float4 a4 = *(const float4*)&As[tid * PS + j];
            rs += a4.x + a4.y + a4.z + a4.w;
        }
        dens[tid] += rs;
    }
#pragma unroll
    for (int i = tid; i < 4096; i += 256) {
        int t = i >> 6, d = i & 63;
        int row = b * LL + c * CHUNK + t;
        Ts[t * PS + d] = qkv[row * 768 + 512 + h * 64 + d];
    }
    __syncthreads();

    // acc += A @ V
#pragma unroll 2
    for (int j = 0; j < 64; j += 4) {
        float av[4][4], vv[4][4];
#pragma unroll
        for (int i = 0; i < 4; i++)
            *(float4*)av[i] = *(const float4*)&As[(i0 + i) * PS + j];
#pragma unroll
        for (int m = 0; m < 4; m++)
            *(float4*)vv[m] = *(const float4*)&Ts[(j + m) * PS + j0];
#pragma unroll
        for (int i = 0; i < 4; i++)
#pragma unroll
            for (int jj = 0; jj < 4; jj++)
#pragma unroll
                for (int m = 0; m < 4; m++)
                    acc[i][jj] += av[i][m] * vv[m][jj];
    }

#pragma unroll
    for (int i = 0; i < 4; i++) {
        float dn = fmaxf(dens[i0 + i], 1e-6f);
        int row = b * LL + c * CHUNK + i0 + i;
        float inv = 1.0f / dn;
        size_t idx = (size_t)row * EE + h * 64 + j0;
        __nv_bfloat162 hp0, hp1, lp0, lp1;
        float v0 = acc[i][0] * inv, v1 = acc[i][1] * inv;
        float v2 = acc[i][2] * inv, v3 = acc[i][3] * inv;
        __nv_bfloat16 h0 = __float2bfloat16(v0), h1 = __float2bfloat16(v1);
        __nv_bfloat16 h2 = __float2bfloat16(v2), h3 = __float2bfloat16(v3);
        hp0.x = h0; hp0.y = h1; hp1.x = h2; hp1.y = h3;
        lp0.x = __float2bfloat16(v0 - __bfloat162float(h0));
        lp0.y = __float2bfloat16(v1 - __bfloat162float(h1));
        lp1.x = __float2bfloat16(v2 - __bfloat162float(h2));
        lp1.y = __float2bfloat16(v3 - __bfloat162float(h3));
        uint2 hh, ll;
        hh.x = *(uint32_t*)&hp0; hh.y = *(uint32_t*)&hp1;
        ll.x = *(uint32_t*)&lp0; ll.y = *(uint32_t*)&lp1;
        *(uint2*)&oh[idx] = hh;
        *(uint2*)&ol[idx] = ll;
    }
}

// ---------------- pred: state tokens @ pred_w + pred_b ---------------------
__global__ __launch_bounds__(256) void pred_kernel(
    const float* __restrict__ xn, const float* __restrict__ pred_w,
    const float* __restrict__ pred_b, float* __restrict__ out)
{
    int bk = blockIdx.x;
    int b = bk / KSTEP, k = bk % KSTEP;
    int row = b * LL + 3 * k + 1;
    __shared__ float xr[EE];
    int tid = threadIdx.x;
    xr[tid] = xn[row * EE + tid];
    __syncthreads();
    int w = tid >> 5, lane = tid & 31;
    if (w < NACT) {
        float s = 0.f;
        for (int e = lane; e < EE; e += 32) s += xr[e] * pred_w[e * NACT + w];
#pragma unroll
        for (int o = 16; o; o >>= 1) s += __shfl_xor_sync(0xffffffffu, s, o);
        if (lane == 0) out[bk * NACT + w] = s + pred_b[w];
    }
}

// ---------------- launch ----------------------------------------------------
extern "C" void kernel_launch(void* const* d_in, const int* in_sizes, int n_in,
                              void* d_out, int out_size)
{
    const float* rtg      = (const float*)d_in[0];
    const float* state    = (const float*)d_in[1];
    const float* action   = (const float*)d_in[2];
    const float* rtg_w    = (const float*)d_in[3];
    const float* rtg_b    = (const float*)d_in[4];
    const float* state_w  = (const float*)d_in[5];
    const float* state_b  = (const float*)d_in[6];
    const float* action_w = (const float*)d_in[7];
    const float* action_b = (const float*)d_in[8];
    const float* pos_emb  = (const float*)d_in[9];
    const float* norm1_g  = (const float*)d_in[10];
    const float* norm1_b  = (const float*)d_in[11];
    const float* qkv_w    = (const float*)d_in[12];
    const float* qkv_b    = (const float*)d_in[13];
    const float* out_w    = (const float*)d_in[14];
    const float* out_b    = (const float*)d_in[15];
    const float* norm2_g  = (const float*)d_in[16];
    const float* norm2_b  = (const float*)d_in[17];
    const float* ffn1_w   = (const float*)d_in[18];
    const float* ffn1_b   = (const float*)d_in[19];
    const float* ffn2_w   = (const float*)d_in[20];
    const float* ffn2_b   = (const float*)d_in[21];
    const float* normf_g  = (const float*)d_in[22];
    const float* normf_b  = (const float*)d_in[23];
    const float* pred_w   = (const float*)d_in[24];
    const float* pred_b   = (const float*)d_in[25];

    float *x, *xn, *qkv, *S, *ks;
    __nv_bfloat16 *xh, *xl, *oh, *ol, *ffh, *ffl, *wh, *wl;
    cudaGetSymbolAddress((void**)&x,   g_x);
    cudaGetSymbolAddress((void**)&xn,  g_xn);
    cudaGetSymbolAddress((void**)&qkv, g_qkv);
    cudaGetSymbolAddress((void**)&S,   g_S);
    cudaGetSymbolAddress((void**)&ks,  g_ks);
    cudaGetSymbolAddress((void**)&xh,  g_xh);
    cudaGetSymbolAddress((void**)&xl,  g_xl);
    cudaGetSymbolAddress((void**)&oh,  g_oh);
    cudaGetSymbolAddress((void**)&ol,  g_ol);
    cudaGetSymbolAddress((void**)&ffh, g_ffh);
    cudaGetSymbolAddress((void**)&ffl, g_ffl);
    cudaGetSymbolAddress((void**)&wh,  g_wh);
    cudaGetSymbolAddress((void**)&wl,  g_wl);

    const int SMEM_C    = (192 * PS + 128) * sizeof(float);  // 52736
    const int SMEM_G128 = 3 * 30720;
    const int SMEM_G64  = 3 * 20480;
    cudaFuncSetAttribute(attn_out_kernel,
                         cudaFuncAttributeMaxDynamicSharedMemorySize, SMEM_C);
    cudaFuncSetAttribute((const void*)gemm_mma_kernel<128, 0>,
                         cudaFuncAttributeMaxDynamicSharedMemorySize, SMEM_G128);
    cudaFuncSetAttribute((const void*)gemm_mma_kernel<128, 1>,
                         cudaFuncAttributeMaxDynamicSharedMemorySize, SMEM_G128);
    cudaFuncSetAttribute((const void*)gemm_mma_kernel<64, 2>,
                         cudaFuncAttributeMaxDynamicSharedMemorySize, SMEM_G64);

    wsplit_kernel<<<dim3(32, 32, 8), dim3(32, 8)>>>(qkv_w, out_w, ffn1_w, ffn2_w, wh, wl);

    embed_ln_kernel<<<MTOK, 256>>>(rtg, state, action, rtg_w, rtg_b, state_w, state_b,
                                   action_w, action_b, pos_emb,
                                   norm1_g, norm1_b, x, xh, xl);

    for (int layer = 0; layer < NLAYER; layer++) {
        const float* n2g = norm2_g + layer * EE;
        const float* n2b = norm2_b + layer * EE;
        const float* qb  = qkv_b  + layer * 3 * EE;
        const float* ob  = out_b  + layer * EE;
        const float* f1b = ffn1_b + layer * FFD;
        const float* f2b = ffn2_b + layer * EE;
        size_t qoff  = (size_t)layer * 196608;
        size_t ooff  = 393216  + (size_t)layer * 65536;
        size_t f1off = 524288  + (size_t)layer * 262144;
        size_t f2off = 1048576 + (size_t)layer * 262144;

        if (layer > 0) {
            ln4_kernel<<<MTOK / 4, 256>>>(x, norm1_g + layer * EE, norm1_b + layer * EE,
                                          xn, xh, xl);
        }

        gemm_mma_kernel<128, 0><<<dim3(12, 24), 256, SMEM_G128>>>(
            xh, xl, wh + qoff, wl + qoff, qb, nullptr, qkv, nullptr, nullptr, 768, 256);

        attn_chunksum_kernel<<<NBH * NCH, 256>>>(qkv, S, ks);
        attn_scan_kernel<<<NBH * 16, 256>>>(S, ks);
        attn_out_kernel<<<NBH * NCH, 256, SMEM_C>>>(qkv, S, ks, oh, ol);

        gemm_mma_kernel<64, 2><<<dim3(4, 48), 128, SMEM_G64>>>(
            oh, ol, wh + ooff, wl + ooff, ob, x, x, nullptr, nullptr, 256, 256);

        ln4_kernel<<<MTOK / 4, 256>>>(x, n2g, n2b, xn, xh, xl);

        gemm_mma_kernel<128, 1><<<dim3(16, 24), 256, SMEM_G128>>>(
            xh, xl, wh + f1off, wl + f1off, f1b, nullptr, nullptr, ffh, ffl, 1024, 256);

        gemm_mma_kernel<64, 2><<<dim3(4, 48), 128, SMEM_G64>>>(
            ffh, ffl, wh + f2off, wl + f2off, f2b, x, x, nullptr, nullptr, 256, 1024);
    }

    ln4_kernel<<<MTOK / 4, 256>>>(x, normf_g, normf_b, xn, xh, xl);
    pred_kernel<<<BB * KSTEP, 256>>>(xn, pred_w, pred_b, (float*)d_out);
}